// round 2
// baseline (speedup 1.0000x reference)
#include <cuda_runtime.h>
#include <cuda_bf16.h>
#include <math.h>

#define B_  2
#define T_  1024
#define C_  4096
#define H_  32
#define G_  8
#define D_  128

// Scratch (allocation-free rule: __device__ globals)
__device__ float g_q  [B_ * T_ * H_ * D_];   // [B*T, H*D]
__device__ float g_k  [B_ * T_ * G_ * D_];   // [B*T, G*D]
__device__ float g_v  [B_ * T_ * G_ * D_];   // [B*T, G*D]
__device__ float g_att[B_ * T_ * H_ * D_];   // [B*T, H*D]

// ---------------------------------------------------------------------------
// Classic 128x128x8 fp32 SGEMM, 256 threads, 8x8 microtile, optional bias.
// C[M,N] = A[M,K] @ B[K,N] (+ bias[N]). M%128==0, N%128==0, K%8==0 assumed.
// ---------------------------------------------------------------------------
__global__ __launch_bounds__(256, 2)
void sgemm_kernel(const float* __restrict__ A, const float* __restrict__ Bm,
                  const float* __restrict__ bias, float* __restrict__ Cm,
                  int M, int N, int K)
{
    const int BM = 128, BN = 128, BK = 8, TM = 8, TN = 8;
    __shared__ float As[BK][BM];   // transposed A tile
    __shared__ float Bs[BK][BN];

    const int tid = threadIdx.x;
    const int tx  = tid & 15;      // 0..15 (N dir)
    const int ty  = tid >> 4;      // 0..15 (M dir)
    const int bx  = blockIdx.x;    // N tile
    const int by  = blockIdx.y;    // M tile

    const float* Ab = A  + (size_t)by * BM * K;
    const float* Bb = Bm + (size_t)bx * BN;

    const int aRow = tid >> 1;          // 0..127
    const int aCol = (tid & 1) * 4;     // 0 or 4
    const int bRow = tid >> 5;          // 0..7
    const int bCol = (tid & 31) * 4;    // 0..124

    float acc[TM][TN];
#pragma unroll
    for (int i = 0; i < TM; i++)
#pragma unroll
        for (int j = 0; j < TN; j++) acc[i][j] = 0.f;

    for (int k0 = 0; k0 < K; k0 += BK) {
        float4 a4 = *(const float4*)(Ab + (size_t)aRow * K + k0 + aCol);
        As[aCol + 0][aRow] = a4.x;
        As[aCol + 1][aRow] = a4.y;
        As[aCol + 2][aRow] = a4.z;
        As[aCol + 3][aRow] = a4.w;
        float4 b4 = *(const float4*)(Bb + (size_t)(k0 + bRow) * N + bCol);
        *(float4*)(&Bs[bRow][bCol]) = b4;
        __syncthreads();

#pragma unroll
        for (int kk = 0; kk < BK; kk++) {
            float ar[TM], br[TN];
#pragma unroll
            for (int i = 0; i < TM; i++) ar[i] = As[kk][ty * TM + i];
#pragma unroll
            for (int j = 0; j < TN; j++) br[j] = Bs[kk][tx * TN + j];
#pragma unroll
            for (int i = 0; i < TM; i++)
#pragma unroll
                for (int j = 0; j < TN; j++)
                    acc[i][j] = fmaf(ar[i], br[j], acc[i][j]);
        }
        __syncthreads();
    }

    const int col0 = bx * BN + tx * TN;
#pragma unroll
    for (int i = 0; i < TM; i++) {
        const int row = by * BM + ty * TM + i;
        float4 o0 = make_float4(acc[i][0], acc[i][1], acc[i][2], acc[i][3]);
        float4 o1 = make_float4(acc[i][4], acc[i][5], acc[i][6], acc[i][7]);
        if (bias) {
            o0.x += bias[col0 + 0]; o0.y += bias[col0 + 1];
            o0.z += bias[col0 + 2]; o0.w += bias[col0 + 3];
            o1.x += bias[col0 + 4]; o1.y += bias[col0 + 5];
            o1.z += bias[col0 + 6]; o1.w += bias[col0 + 7];
        }
        float* cp = Cm + (size_t)row * N + col0;
        *(float4*)(cp)     = o0;
        *(float4*)(cp + 4) = o1;
    }
}

// ---------------------------------------------------------------------------
// RoPE in-place on a [B*T, nh*D] buffer. One thread per (row, head, d2) pair.
// Uses accurate sincosf (angles up to ~1023 rad; __sincosf mis-reduces there).
// ---------------------------------------------------------------------------
__global__ void rope_kernel(float* __restrict__ p, int nh, int total)
{
    int idx = blockIdx.x * blockDim.x + threadIdx.x;
    if (idx >= total) return;
    const int d2  = idx & 63;
    const int h   = (idx >> 6) % nh;
    const int row = idx / (64 * nh);
    const int t   = row % T_;

    const float inv_freq = powf(10000.0f, -(float)d2 / 64.0f);
    const float ang = (float)t * inv_freq;
    float s, c;
    sincosf(ang, &s, &c);

    const size_t off = (size_t)row * nh * D_ + (size_t)h * D_ + 2 * d2;
    const float xr = p[off], xi = p[off + 1];
    p[off]     = xr * c - xi * s;
    p[off + 1] = xr * s + xi * c;
}

// ---------------------------------------------------------------------------
// Causal GQA attention. Block = (query tile of 8, head, batch), 256 threads
// (8 warps; warp w owns query row w of the tile). K/V staged through smem in
// 32-row tiles; full score rows (8 x 1024) live in smem (no online softmax).
// smem = 8*1024 + 32*128 floats = 49152 bytes.
// ---------------------------------------------------------------------------
#define BQ 8
#define SK 32

__global__ __launch_bounds__(256)
void attn_kernel(const float* __restrict__ q, const float* __restrict__ k,
                 const float* __restrict__ v, float* __restrict__ out)
{
    extern __shared__ float sm[];
    float* sc = sm;             // [BQ][T_]
    float* kv = sm + BQ * T_;   // [SK][D_]

    const int tq  = blockIdx.x;        // 0..T_/BQ-1
    const int h   = blockIdx.y;        // 0..H_-1
    const int b   = blockIdx.z;        // 0..B_-1
    const int g   = h >> 2;            // H_/G_ = 4 heads per group
    const int tid = threadIdx.x;
    const int lane = tid & 31;
    const int w    = tid >> 5;         // 0..7: warp == query row in tile

    const int base = tq * BQ;
    const int tQ   = base + w;         // this warp's query index
    const int Smax = base + BQ;        // need scores for s in [0, Smax)
    const int Send = ((Smax + SK - 1) / SK) * SK;   // padded; extras masked

    // q row in registers (lane covers d = lane + 32j)
    float rq[4];
    {
        const float* qr = q + (((size_t)b * T_ + tQ) * H_ + h) * D_;
#pragma unroll
        for (int j = 0; j < 4; j++) rq[j] = qr[lane + 32 * j];
    }
    const float scale = 0.08838834764831845f;  // 1/sqrt(128)

    // ---- Phase 1: scores ----
    for (int s0 = 0; s0 < Smax; s0 += SK) {
        __syncthreads();   // previous kv tile fully consumed
        {
            const int r = tid >> 3;          // 0..31
            const int c = (tid & 7) * 16;    // 0..112
            const float* kr = k + (((size_t)b * T_ + (s0 + r)) * G_ + g) * D_;
            float4* dst = (float4*)(kv + r * D_ + c);
            const float4* src = (const float4*)(kr + c);
            dst[0] = src[0]; dst[1] = src[1]; dst[2] = src[2]; dst[3] = src[3];
        }
        __syncthreads();
#pragma unroll 4
        for (int si = 0; si < SK; si++) {
            const int s = s0 + si;
            const float* kk = kv + si * D_;
            float p = 0.f;
#pragma unroll
            for (int j = 0; j < 4; j++) p = fmaf(rq[j], kk[lane + 32 * j], p);
#pragma unroll
            for (int o = 16; o; o >>= 1) p += __shfl_xor_sync(0xffffffffu, p, o);
            if (lane == 0) sc[w * T_ + s] = (s <= tQ) ? p * scale : -1e30f;
        }
    }
    __syncthreads();

    // pad region [Smax, Send): mask so softmax ignores it
    for (int s = Smax + lane; s < Send; s += 32) sc[w * T_ + s] = -1e30f;
    __syncwarp();

    // ---- Phase 2: softmax over own row (per warp) ----
    float m = -1e30f;
    for (int s = lane; s < Send; s += 32) m = fmaxf(m, sc[w * T_ + s]);
#pragma unroll
    for (int o = 16; o; o >>= 1) m = fmaxf(m, __shfl_xor_sync(0xffffffffu, m, o));
    float lsum = 0.f;
    for (int s = lane; s < Send; s += 32) {
        const float e = __expf(sc[w * T_ + s] - m);
        sc[w * T_ + s] = e;
        lsum += e;
    }
#pragma unroll
    for (int o = 16; o; o >>= 1) lsum += __shfl_xor_sync(0xffffffffu, lsum, o);
    const float inv = 1.0f / lsum;

    // ---- Phase 3: probs @ V ----
    float a0 = 0.f, a1 = 0.f, a2 = 0.f, a3 = 0.f;
    for (int s0 = 0; s0 < Smax; s0 += SK) {
        __syncthreads();   // previous kv tile consumed / sc finalized
        {
            const int r = tid >> 3;
            const int c = (tid & 7) * 16;
            const float* vr = v + (((size_t)b * T_ + (s0 + r)) * G_ + g) * D_;
            float4* dst = (float4*)(kv + r * D_ + c);
            const float4* src = (const float4*)(vr + c);
            dst[0] = src[0]; dst[1] = src[1]; dst[2] = src[2]; dst[3] = src[3];
        }
        __syncthreads();
        const float* scrow = sc + w * T_ + s0;
#pragma unroll 8
        for (int si = 0; si < SK; si++) {
            const float p = scrow[si];
            const float* vrow = kv + si * D_;
            a0 = fmaf(p, vrow[lane],      a0);
            a1 = fmaf(p, vrow[lane + 32], a1);
            a2 = fmaf(p, vrow[lane + 64], a2);
            a3 = fmaf(p, vrow[lane + 96], a3);
        }
    }

    const size_t o = (((size_t)b * T_ + tQ) * H_ + h) * D_;
    out[o + lane]      = a0 * inv;
    out[o + lane + 32] = a1 * inv;
    out[o + lane + 64] = a2 * inv;
    out[o + lane + 96] = a3 * inv;
}

// ---------------------------------------------------------------------------
extern "C" void kernel_launch(void* const* d_in, const int* in_sizes, int n_in,
                              void* d_out, int out_size)
{
    const float* x  = (const float*)d_in[0];
    const float* Wq = (const float*)d_in[1];
    const float* Wk = (const float*)d_in[2];
    const float* Wv = (const float*)d_in[3];
    const float* Wo = (const float*)d_in[4];
    const float* bo = (const float*)d_in[5];
    float* out = (float*)d_out;

    float *q, *k, *v, *att;
    cudaGetSymbolAddress((void**)&q,   g_q);
    cudaGetSymbolAddress((void**)&k,   g_k);
    cudaGetSymbolAddress((void**)&v,   g_v);
    cudaGetSymbolAddress((void**)&att, g_att);

    const int M = B_ * T_;          // 2048

    // QKV projections
    sgemm_kernel<<<dim3(H_ * D_ / 128, M / 128), 256>>>(x, Wq, nullptr, q, M, H_ * D_, C_);
    sgemm_kernel<<<dim3(G_ * D_ / 128, M / 128), 256>>>(x, Wk, nullptr, k, M, G_ * D_, C_);
    sgemm_kernel<<<dim3(G_ * D_ / 128, M / 128), 256>>>(x, Wv, nullptr, v, M, G_ * D_, C_);

    // RoPE on q and k
    {
        const int nq = B_ * T_ * H_ * 64;
        rope_kernel<<<(nq + 255) / 256, 256>>>(q, H_, nq);
        const int nk = B_ * T_ * G_ * 64;
        rope_kernel<<<(nk + 255) / 256, 256>>>(k, G_, nk);
    }

    // Attention
    {
        const int smem = (BQ * T_ + SK * D_) * (int)sizeof(float);   // 49152
        cudaFuncSetAttribute(attn_kernel,
                             cudaFuncAttributeMaxDynamicSharedMemorySize, smem);
        attn_kernel<<<dim3(T_ / BQ, H_, B_), 256, smem>>>(q, k, v, att);
    }

    // Output projection + bias
    sgemm_kernel<<<dim3(C_ / 128, M / 128), 256>>>(att, Wo, bo, out, M, C_, C_);
}

// round 5
// speedup vs baseline: 1.6753x; 1.6753x over previous
#include <cuda_runtime.h>
#include <cuda_bf16.h>
#include <math.h>
#include <stdint.h>

#define B_  2
#define T_  1024
#define C_  4096
#define H_  32
#define G_  8
#define D_  128
#define M_  (B_*T_)          // 2048 rows

// ---------------- scratch (__device__ globals; no allocs allowed) ----------
__device__ float g_q  [M_ * H_ * D_];
__device__ float g_k  [M_ * G_ * D_];
__device__ float g_v  [M_ * G_ * D_];
__device__ float g_att[M_ * H_ * D_];

__device__ __nv_bfloat16 g_xh [M_ * C_];
__device__ __nv_bfloat16 g_xl [M_ * C_];
__device__ __nv_bfloat16 g_ath[M_ * C_];
__device__ __nv_bfloat16 g_atl[M_ * C_];
// transposed weights, [N, K] K-major, bf16 hi/lo
__device__ __nv_bfloat16 g_wqh[(H_*D_) * C_];
__device__ __nv_bfloat16 g_wql[(H_*D_) * C_];
__device__ __nv_bfloat16 g_wkh[(G_*D_) * C_];
__device__ __nv_bfloat16 g_wkl[(G_*D_) * C_];
__device__ __nv_bfloat16 g_wvh[(G_*D_) * C_];
__device__ __nv_bfloat16 g_wvl[(G_*D_) * C_];
__device__ __nv_bfloat16 g_woh[C_ * (H_*D_)];
__device__ __nv_bfloat16 g_wol[C_ * (H_*D_)];

// ---------------- helpers ---------------------------------------------------
__device__ __forceinline__ uint32_t smem_u32(const void* p) {
    uint32_t a;
    asm("{ .reg .u64 t; cvta.to.shared.u64 t, %1; cvt.u32.u64 %0, t; }"
        : "=r"(a) : "l"(p));
    return a;
}
__device__ __forceinline__ void cp16(uint32_t dst, const void* src) {
    asm volatile("cp.async.cg.shared.global [%0], [%1], 16;"
                 :: "r"(dst), "l"(src) : "memory");
}
__device__ __forceinline__ void cp_commit() {
    asm volatile("cp.async.commit_group;" ::: "memory");
}
template <int N>
__device__ __forceinline__ void cp_wait() {
    asm volatile("cp.async.wait_group %0;" :: "n"(N) : "memory");
}
__device__ __forceinline__ void mma_bf16(float* c, const uint32_t* a, const uint32_t* b) {
    asm volatile(
        "mma.sync.aligned.m16n8k16.row.col.f32.bf16.bf16.f32 "
        "{%0,%1,%2,%3}, {%4,%5,%6,%7}, {%8,%9}, {%0,%1,%2,%3};"
        : "+f"(c[0]), "+f"(c[1]), "+f"(c[2]), "+f"(c[3])
        : "r"(a[0]), "r"(a[1]), "r"(a[2]), "r"(a[3]), "r"(b[0]), "r"(b[1]));
}

// ---------------------------------------------------------------------------
// bf16x3 HMMA GEMM: C[M,N] = A[M,K] @ Wt[N,K]^T (+bias), fp32 accumulate.
// CTA tile 128x128, BK=32, 256 threads (8 warps, 4(m) x 2(n)); warp tile 32x64.
// smem rows padded to 40 bf16 (80B) -> conflict-free frag loads.
// cp.async double-buffered stages.
// ---------------------------------------------------------------------------
#define SA 40                                 // padded row stride (bf16)
#define MAT_BYTES (128 * SA * 2)              // 10240 bytes per matrix tile
#define STAGE_BYTES (4 * MAT_BYTES)           // Ah, Al, Bh, Bl
#define GEMM_SMEM (2 * STAGE_BYTES)           // 81920

__global__ __launch_bounds__(256, 1)
void gemm_mma_kernel(const __nv_bfloat16* __restrict__ Ah, const __nv_bfloat16* __restrict__ Al,
                     const __nv_bfloat16* __restrict__ Bh, const __nv_bfloat16* __restrict__ Bl,
                     const float* __restrict__ bias, float* __restrict__ Cm,
                     int Ndim, int Kdim)
{
    extern __shared__ char sm[];
    const uint32_t smb = smem_u32(sm);
    const int tid  = threadIdx.x;
    const int lane = tid & 31;
    const int w    = tid >> 5;
    const int wm   = w & 3;            // 0..3  (m slice of 32)
    const int wn   = w >> 2;           // 0..1  (n slice of 64)
    const int gg   = lane >> 2;        // group 0..7
    const int tt   = lane & 3;         // 0..3
    const int m0   = blockIdx.y * 128;
    const int n0   = blockIdx.x * 128;

    const int nchunks = Kdim >> 5;     // BK = 32

    // per-thread cp.async assignment: 2048 16B-chunks per stage, 8 per thread
    // chunk i: matrix = i>>9 (0 Ah,1 Al,2 Bh,3 Bl), idx = i & 511, r = idx>>2, s = idx&3
    const __nv_bfloat16* gsrc[4] = { Ah, Al, Bh, Bl };

    auto issue_stage = [&](int c, int st) {
        const int k0 = c << 5;
#pragma unroll
        for (int j = 0; j < 8; j++) {
            const int i   = tid + (j << 8);
            const int mat = i >> 9;
            const int idx = i & 511;
            const int r   = idx >> 2;
            const int s   = idx & 3;
            const int grow = (mat < 2) ? (m0 + r) : (n0 + r);
            const __nv_bfloat16* src = gsrc[mat] + (size_t)grow * Kdim + k0 + s * 8;
            const uint32_t dst = smb + st * STAGE_BYTES + mat * MAT_BYTES + r * (SA * 2) + s * 16;
            cp16(dst, src);
        }
        cp_commit();
    };

    float acc[2][8][4];
#pragma unroll
    for (int i = 0; i < 2; i++)
#pragma unroll
        for (int j = 0; j < 8; j++)
#pragma unroll
            for (int l = 0; l < 4; l++) acc[i][j][l] = 0.f;

    issue_stage(0, 0);

    for (int c = 0; c < nchunks; ++c) {
        const int st = c & 1;
        if (c + 1 < nchunks) { issue_stage(c + 1, st ^ 1); cp_wait<1>(); }
        else                 { cp_wait<0>(); }
        __syncthreads();

        const char* As_h = sm + st * STAGE_BYTES;
        const char* As_l = As_h + MAT_BYTES;
        const char* Bs_h = As_h + 2 * MAT_BYTES;
        const char* Bs_l = As_h + 3 * MAT_BYTES;

#pragma unroll
        for (int k16 = 0; k16 < 32; k16 += 16) {
            // A fragments (2 m-tiles, hi & lo)
            uint32_t ah[2][4], al[2][4];
#pragma unroll
            for (int mt = 0; mt < 2; mt++) {
                const int row = wm * 32 + mt * 16 + gg;
                const int col = k16 + 2 * tt;
                const int o00 = row * (SA * 2) + col * 2;
                const int o10 = (row + 8) * (SA * 2) + col * 2;
                ah[mt][0] = *(const uint32_t*)(As_h + o00);
                ah[mt][1] = *(const uint32_t*)(As_h + o10);
                ah[mt][2] = *(const uint32_t*)(As_h + o00 + 16);
                ah[mt][3] = *(const uint32_t*)(As_h + o10 + 16);
                al[mt][0] = *(const uint32_t*)(As_l + o00);
                al[mt][1] = *(const uint32_t*)(As_l + o10);
                al[mt][2] = *(const uint32_t*)(As_l + o00 + 16);
                al[mt][3] = *(const uint32_t*)(As_l + o10 + 16);
            }
#pragma unroll
            for (int nt = 0; nt < 8; nt++) {
                const int nrow = wn * 64 + nt * 8 + gg;
                const int o = nrow * (SA * 2) + (k16 + 2 * tt) * 2;
                uint32_t bh[2], bl[2];
                bh[0] = *(const uint32_t*)(Bs_h + o);
                bh[1] = *(const uint32_t*)(Bs_h + o + 16);
                bl[0] = *(const uint32_t*)(Bs_l + o);
                bl[1] = *(const uint32_t*)(Bs_l + o + 16);
#pragma unroll
                for (int mt = 0; mt < 2; mt++) {
                    mma_bf16(acc[mt][nt], ah[mt], bh);
                    mma_bf16(acc[mt][nt], ah[mt], bl);
                    mma_bf16(acc[mt][nt], al[mt], bh);
                }
            }
        }
        __syncthreads();
    }

    // epilogue
#pragma unroll
    for (int mt = 0; mt < 2; mt++) {
#pragma unroll
        for (int nt = 0; nt < 8; nt++) {
            const int row = m0 + wm * 32 + mt * 16 + gg;
            const int col = n0 + wn * 64 + nt * 8 + 2 * tt;
            float2 v0 = make_float2(acc[mt][nt][0], acc[mt][nt][1]);
            float2 v1 = make_float2(acc[mt][nt][2], acc[mt][nt][3]);
            if (bias) {
                v0.x += bias[col]; v0.y += bias[col + 1];
                v1.x += bias[col]; v1.y += bias[col + 1];
            }
            *(float2*)(Cm + (size_t)row * Ndim + col)       = v0;
            *(float2*)(Cm + (size_t)(row + 8) * Ndim + col) = v1;
        }
    }
}

// ---------------- fp32 -> bf16 hi/lo split ---------------------------------
__global__ void split_kernel(const float* __restrict__ src,
                             __nv_bfloat16* __restrict__ hi,
                             __nv_bfloat16* __restrict__ lo, int n)
{
    int i = blockIdx.x * blockDim.x + threadIdx.x;
    if (i >= n) return;
    float a = src[i];
    __nv_bfloat16 h = __float2bfloat16(a);
    hi[i] = h;
    lo[i] = __float2bfloat16(a - __bfloat162float(h));
}

// ---------------- transpose + split: W[K,N] -> Wt_hi/lo[N,K] ---------------
__global__ void transpose_split_kernel(const float* __restrict__ W,
                                       __nv_bfloat16* __restrict__ Th,
                                       __nv_bfloat16* __restrict__ Tl,
                                       int Kdim, int Ndim)
{
    __shared__ float t[32][33];
    const int n0 = blockIdx.x * 32, k0 = blockIdx.y * 32;
    const int tx = threadIdx.x, ty = threadIdx.y;
#pragma unroll
    for (int j = 0; j < 32; j += 8)
        t[ty + j][tx] = W[(size_t)(k0 + ty + j) * Ndim + n0 + tx];
    __syncthreads();
#pragma unroll
    for (int j = 0; j < 32; j += 8) {
        float a = t[tx][ty + j];
        __nv_bfloat16 h = __float2bfloat16(a);
        size_t o = (size_t)(n0 + ty + j) * Kdim + k0 + tx;
        Th[o] = h;
        Tl[o] = __float2bfloat16(a - __bfloat162float(h));
    }
}

// ---------------- RoPE ------------------------------------------------------
__global__ void rope_kernel(float* __restrict__ p, int nh, int total)
{
    int idx = blockIdx.x * blockDim.x + threadIdx.x;
    if (idx >= total) return;
    const int d2  = idx & 63;
    const int h   = (idx >> 6) % nh;
    const int row = idx / (64 * nh);
    const int t   = row % T_;

    const float inv_freq = powf(10000.0f, -(float)d2 / 64.0f);
    float s, c;
    sincosf((float)t * inv_freq, &s, &c);

    const size_t off = (size_t)row * nh * D_ + (size_t)h * D_ + 2 * d2;
    const float xr = p[off], xi = p[off + 1];
    p[off]     = xr * c - xi * s;
    p[off + 1] = xr * s + xi * c;
}

// ---------------- attention (proven in R1) ---------------------------------
#define BQ 8
#define SK 32

__global__ __launch_bounds__(256)
void attn_kernel(const float* __restrict__ q, const float* __restrict__ k,
                 const float* __restrict__ v, float* __restrict__ out)
{
    extern __shared__ float smf[];
    float* sc = smf;             // [BQ][T_]
    float* kv = smf + BQ * T_;   // [SK][D_]

    const int tq  = blockIdx.x;
    const int h   = blockIdx.y;
    const int b   = blockIdx.z;
    const int g   = h >> 2;
    const int tid = threadIdx.x;
    const int lane = tid & 31;
    const int w    = tid >> 5;

    const int base = tq * BQ;
    const int tQ   = base + w;
    const int Smax = base + BQ;
    const int Send = ((Smax + SK - 1) / SK) * SK;

    float rq[4];
    {
        const float* qr = q + (((size_t)b * T_ + tQ) * H_ + h) * D_;
#pragma unroll
        for (int j = 0; j < 4; j++) rq[j] = qr[lane + 32 * j];
    }
    const float scale = 0.08838834764831845f;

    for (int s0 = 0; s0 < Smax; s0 += SK) {
        __syncthreads();
        {
            const int r = tid >> 3;
            const int c = (tid & 7) * 16;
            const float* kr = k + (((size_t)b * T_ + (s0 + r)) * G_ + g) * D_;
            float4* dst = (float4*)(kv + r * D_ + c);
            const float4* src = (const float4*)(kr + c);
            dst[0] = src[0]; dst[1] = src[1]; dst[2] = src[2]; dst[3] = src[3];
        }
        __syncthreads();
#pragma unroll 4
        for (int si = 0; si < SK; si++) {
            const int s = s0 + si;
            const float* kk = kv + si * D_;
            float p = 0.f;
#pragma unroll
            for (int j = 0; j < 4; j++) p = fmaf(rq[j], kk[lane + 32 * j], p);
#pragma unroll
            for (int o = 16; o; o >>= 1) p += __shfl_xor_sync(0xffffffffu, p, o);
            if (lane == 0) sc[w * T_ + s] = (s <= tQ) ? p * scale : -1e30f;
        }
    }
    __syncthreads();

    for (int s = Smax + lane; s < Send; s += 32) sc[w * T_ + s] = -1e30f;
    __syncwarp();

    float m = -1e30f;
    for (int s = lane; s < Send; s += 32) m = fmaxf(m, sc[w * T_ + s]);
#pragma unroll
    for (int o = 16; o; o >>= 1) m = fmaxf(m, __shfl_xor_sync(0xffffffffu, m, o));
    float lsum = 0.f;
    for (int s = lane; s < Send; s += 32) {
        const float e = __expf(sc[w * T_ + s] - m);
        sc[w * T_ + s] = e;
        lsum += e;
    }
#pragma unroll
    for (int o = 16; o; o >>= 1) lsum += __shfl_xor_sync(0xffffffffu, lsum, o);
    const float inv = 1.0f / lsum;

    float a0 = 0.f, a1 = 0.f, a2 = 0.f, a3 = 0.f;
    for (int s0 = 0; s0 < Smax; s0 += SK) {
        __syncthreads();
        {
            const int r = tid >> 3;
            const int c = (tid & 7) * 16;
            const float* vr = v + (((size_t)b * T_ + (s0 + r)) * G_ + g) * D_;
            float4* dst = (float4*)(kv + r * D_ + c);
            const float4* src = (const float4*)(vr + c);
            dst[0] = src[0]; dst[1] = src[1]; dst[2] = src[2]; dst[3] = src[3];
        }
        __syncthreads();
        const float* scrow = sc + w * T_ + s0;
#pragma unroll 8
        for (int si = 0; si < SK; si++) {
            const float p = scrow[si];
            const float* vrow = kv + si * D_;
            a0 = fmaf(p, vrow[lane],      a0);
            a1 = fmaf(p, vrow[lane + 32], a1);
            a2 = fmaf(p, vrow[lane + 64], a2);
            a3 = fmaf(p, vrow[lane + 96], a3);
        }
    }

    const size_t o = (((size_t)b * T_ + tQ) * H_ + h) * D_;
    out[o + lane]      = a0 * inv;
    out[o + lane + 32] = a1 * inv;
    out[o + lane + 64] = a2 * inv;
    out[o + lane + 96] = a3 * inv;
}

// ---------------------------------------------------------------------------
extern "C" void kernel_launch(void* const* d_in, const int* in_sizes, int n_in,
                              void* d_out, int out_size)
{
    const float* x  = (const float*)d_in[0];
    const float* Wq = (const float*)d_in[1];
    const float* Wk = (const float*)d_in[2];
    const float* Wv = (const float*)d_in[3];
    const float* Wo = (const float*)d_in[4];
    const float* bo = (const float*)d_in[5];
    float* out = (float*)d_out;

    float *q, *k, *v, *att;
    __nv_bfloat16 *xh, *xl, *ath, *atl;
    __nv_bfloat16 *wqh, *wql, *wkh, *wkl, *wvh, *wvl, *woh, *wol;
    cudaGetSymbolAddress((void**)&q,   g_q);
    cudaGetSymbolAddress((void**)&k,   g_k);
    cudaGetSymbolAddress((void**)&v,   g_v);
    cudaGetSymbolAddress((void**)&att, g_att);
    cudaGetSymbolAddress((void**)&xh,  g_xh);
    cudaGetSymbolAddress((void**)&xl,  g_xl);
    cudaGetSymbolAddress((void**)&ath, g_ath);
    cudaGetSymbolAddress((void**)&atl, g_atl);
    cudaGetSymbolAddress((void**)&wqh, g_wqh);
    cudaGetSymbolAddress((void**)&wql, g_wql);
    cudaGetSymbolAddress((void**)&wkh, g_wkh);
    cudaGetSymbolAddress((void**)&wkl, g_wkl);
    cudaGetSymbolAddress((void**)&wvh, g_wvh);
    cudaGetSymbolAddress((void**)&wvl, g_wvl);
    cudaGetSymbolAddress((void**)&woh, g_woh);
    cudaGetSymbolAddress((void**)&wol, g_wol);

    cudaFuncSetAttribute(gemm_mma_kernel,
                         cudaFuncAttributeMaxDynamicSharedMemorySize, GEMM_SMEM);

    // convert inputs
    split_kernel<<<(M_ * C_ + 255) / 256, 256>>>(x, xh, xl, M_ * C_);
    transpose_split_kernel<<<dim3(H_ * D_ / 32, C_ / 32), dim3(32, 8)>>>(Wq, wqh, wql, C_, H_ * D_);
    transpose_split_kernel<<<dim3(G_ * D_ / 32, C_ / 32), dim3(32, 8)>>>(Wk, wkh, wkl, C_, G_ * D_);
    transpose_split_kernel<<<dim3(G_ * D_ / 32, C_ / 32), dim3(32, 8)>>>(Wv, wvh, wvl, C_, G_ * D_);
    transpose_split_kernel<<<dim3(C_ / 32, (H_ * D_) / 32), dim3(32, 8)>>>(Wo, woh, wol, H_ * D_, C_);

    // QKV projections (HMMA bf16x3)
    gemm_mma_kernel<<<dim3((H_ * D_) / 128, M_ / 128), 256, GEMM_SMEM>>>(
        xh, xl, wqh, wql, nullptr, q, H_ * D_, C_);
    gemm_mma_kernel<<<dim3((G_ * D_) / 128, M_ / 128), 256, GEMM_SMEM>>>(
        xh, xl, wkh, wkl, nullptr, k, G_ * D_, C_);
    gemm_mma_kernel<<<dim3((G_ * D_) / 128, M_ / 128), 256, GEMM_SMEM>>>(
        xh, xl, wvh, wvl, nullptr, v, G_ * D_, C_);

    // RoPE
    rope_kernel<<<(M_ * H_ * 64 + 255) / 256, 256>>>(q, H_, M_ * H_ * 64);
    rope_kernel<<<(M_ * G_ * 64 + 255) / 256, 256>>>(k, G_, M_ * G_ * 64);

    // Attention
    {
        const int smem = (BQ * T_ + SK * D_) * (int)sizeof(float);
        cudaFuncSetAttribute(attn_kernel,
                             cudaFuncAttributeMaxDynamicSharedMemorySize, smem);
        attn_kernel<<<dim3(T_ / BQ, H_, B_), 256, smem>>>(q, k, v, att);
    }

    // Output projection + bias
    split_kernel<<<(M_ * C_ + 255) / 256, 256>>>(att, ath, atl, M_ * C_);
    gemm_mma_kernel<<<dim3(C_ / 128, M_ / 128), 256, GEMM_SMEM>>>(
        ath, atl, woh, wol, bo, out, C_, H_ * D_);
}

// round 6
// speedup vs baseline: 2.3715x; 1.4156x over previous
#include <cuda_runtime.h>
#include <cuda_bf16.h>
#include <math.h>
#include <stdint.h>

#define B_  2
#define T_  1024
#define C_  4096
#define H_  32
#define G_  8
#define D_  128
#define M_  (B_*T_)          // 2048 rows

// ---------------- scratch (__device__ globals; no allocs allowed) ----------
__device__ float g_q  [M_ * H_ * D_];
__device__ float g_k  [M_ * G_ * D_];
__device__ float g_v  [M_ * G_ * D_];
__device__ float g_att[M_ * H_ * D_];

__device__ __nv_bfloat16 g_xh [M_ * C_];
__device__ __nv_bfloat16 g_xl [M_ * C_];
__device__ __nv_bfloat16 g_ath[M_ * C_];
__device__ __nv_bfloat16 g_atl[M_ * C_];
// transposed weights, [N, K] K-major, bf16 hi/lo
__device__ __nv_bfloat16 g_wqh[(H_*D_) * C_];
__device__ __nv_bfloat16 g_wql[(H_*D_) * C_];
__device__ __nv_bfloat16 g_wkh[(G_*D_) * C_];
__device__ __nv_bfloat16 g_wkl[(G_*D_) * C_];
__device__ __nv_bfloat16 g_wvh[(G_*D_) * C_];
__device__ __nv_bfloat16 g_wvl[(G_*D_) * C_];
__device__ __nv_bfloat16 g_woh[C_ * (H_*D_)];
__device__ __nv_bfloat16 g_wol[C_ * (H_*D_)];

// ---------------- helpers ---------------------------------------------------
__device__ __forceinline__ uint32_t smem_u32(const void* p) {
    uint32_t a;
    asm("{ .reg .u64 t; cvta.to.shared.u64 t, %1; cvt.u32.u64 %0, t; }"
        : "=r"(a) : "l"(p));
    return a;
}
__device__ __forceinline__ void cp16(uint32_t dst, const void* src) {
    asm volatile("cp.async.cg.shared.global [%0], [%1], 16;"
                 :: "r"(dst), "l"(src) : "memory");
}
__device__ __forceinline__ void cp_commit() {
    asm volatile("cp.async.commit_group;" ::: "memory");
}
template <int N>
__device__ __forceinline__ void cp_wait() {
    asm volatile("cp.async.wait_group %0;" :: "n"(N) : "memory");
}
__device__ __forceinline__ void mma_bf16(float* c, const uint32_t* a, const uint32_t* b) {
    asm volatile(
        "mma.sync.aligned.m16n8k16.row.col.f32.bf16.bf16.f32 "
        "{%0,%1,%2,%3}, {%4,%5,%6,%7}, {%8,%9}, {%0,%1,%2,%3};"
        : "+f"(c[0]), "+f"(c[1]), "+f"(c[2]), "+f"(c[3])
        : "r"(a[0]), "r"(a[1]), "r"(a[2]), "r"(a[3]), "r"(b[0]), "r"(b[1]));
}
__device__ __forceinline__ void ldsm4(uint32_t* r, uint32_t a) {
    asm volatile("ldmatrix.sync.aligned.m8n8.x4.shared.b16 {%0,%1,%2,%3}, [%4];"
        : "=r"(r[0]), "=r"(r[1]), "=r"(r[2]), "=r"(r[3]) : "r"(a));
}

// ---------------------------------------------------------------------------
// bf16x3 HMMA GEMM: C = A[M,K] @ Wt[N,K]^T (+bias), fp32 accumulate.
// CTA tile 128x128, BK=32, 256 threads (8 warps, 4m x 2n); warp tile 32x64.
// ldmatrix.x4 fragment loads from 80B-padded smem rows; cp.async dbl-buffer.
// blockIdx.z selects (B,C) pointer set (fused K+V projections).
// ---------------------------------------------------------------------------
#define SA 40                                 // padded row stride (bf16)
#define MAT_BYTES (128 * SA * 2)              // 10240 bytes per matrix tile
#define STAGE_BYTES (4 * MAT_BYTES)           // Ah, Al, Bh, Bl
#define GEMM_SMEM (2 * STAGE_BYTES)           // 81920

__global__ __launch_bounds__(256, 2)
void gemm_mma_kernel(const __nv_bfloat16* __restrict__ Ah, const __nv_bfloat16* __restrict__ Al,
                     const __nv_bfloat16* __restrict__ B1h, const __nv_bfloat16* __restrict__ B1l,
                     const __nv_bfloat16* __restrict__ B2h, const __nv_bfloat16* __restrict__ B2l,
                     const float* __restrict__ bias,
                     float* __restrict__ C1, float* __restrict__ C2,
                     int Ndim, int Kdim)
{
    extern __shared__ char sm[];
    const uint32_t smb = smem_u32(sm);
    const int tid  = threadIdx.x;
    const int lane = tid & 31;
    const int w    = tid >> 5;
    const int wm   = w & 3;            // 0..3  (m slice of 32)
    const int wn   = w >> 2;           // 0..1  (n slice of 64)
    const int gg   = lane >> 2;
    const int tt   = lane & 3;
    const int m0   = blockIdx.y * 128;
    const int n0   = blockIdx.x * 128;

    const __nv_bfloat16* Bh = blockIdx.z ? B2h : B1h;
    const __nv_bfloat16* Bl = blockIdx.z ? B2l : B1l;
    float* Cm = blockIdx.z ? C2 : C1;

    const int nchunks = Kdim >> 5;     // BK = 32

    const __nv_bfloat16* gsrc[4] = { Ah, Al, Bh, Bl };

    auto issue_stage = [&](int c, int st) {
        const int k0 = c << 5;
#pragma unroll
        for (int j = 0; j < 8; j++) {
            const int mat = j >> 1;
            const int idx = tid + ((j & 1) << 8);    // 0..511
            const int r   = idx >> 2;
            const int s   = idx & 3;
            const int grow = (mat < 2) ? (m0 + r) : (n0 + r);
            const __nv_bfloat16* src = gsrc[mat] + (size_t)grow * Kdim + k0 + s * 8;
            const uint32_t dst = smb + st * STAGE_BYTES + mat * MAT_BYTES + r * (SA * 2) + s * 16;
            cp16(dst, src);
        }
        cp_commit();
    };

    float acc[2][8][4];
#pragma unroll
    for (int i = 0; i < 2; i++)
#pragma unroll
        for (int j = 0; j < 8; j++)
#pragma unroll
            for (int l = 0; l < 4; l++) acc[i][j][l] = 0.f;

    // per-thread ldmatrix byte offsets (within one matrix tile), before k16 term
    const uint32_t aoff0 = (uint32_t)((wm * 32 + (lane & 7) + ((lane >> 3) & 1) * 8) * (SA * 2)
                                      + (lane >> 4) * 16);
    const uint32_t boff0 = (uint32_t)((wn * 64 + (lane & 7) + ((lane >> 3) & 1) * 8) * (SA * 2)
                                      + (lane >> 4) * 16);

    issue_stage(0, 0);

    for (int c = 0; c < nchunks; ++c) {
        const int st = c & 1;
        if (c + 1 < nchunks) { issue_stage(c + 1, st ^ 1); cp_wait<1>(); }
        else                 { cp_wait<0>(); }
        __syncthreads();

        const uint32_t sAh = smb + st * STAGE_BYTES;
        const uint32_t sAl = sAh + MAT_BYTES;
        const uint32_t sBh = sAh + 2 * MAT_BYTES;
        const uint32_t sBl = sAh + 3 * MAT_BYTES;

#pragma unroll
        for (int k16 = 0; k16 < 32; k16 += 16) {
            uint32_t ah[2][4], al[2][4];
#pragma unroll
            for (int mt = 0; mt < 2; mt++) {
                const uint32_t ao = aoff0 + mt * 16 * (SA * 2) + k16 * 2;
                ldsm4(ah[mt], sAh + ao);
                ldsm4(al[mt], sAl + ao);
            }
#pragma unroll
            for (int nt2 = 0; nt2 < 4; nt2++) {
                const uint32_t bo = boff0 + nt2 * 16 * (SA * 2) + k16 * 2;
                uint32_t bh4[4], bl4[4];
                ldsm4(bh4, sBh + bo);
                ldsm4(bl4, sBl + bo);
                uint32_t bhe[2] = { bh4[0], bh4[2] }, bho[2] = { bh4[1], bh4[3] };
                uint32_t ble[2] = { bl4[0], bl4[2] }, blo[2] = { bl4[1], bl4[3] };
#pragma unroll
                for (int mt = 0; mt < 2; mt++) {
                    mma_bf16(acc[mt][2 * nt2],     ah[mt], bhe);
                    mma_bf16(acc[mt][2 * nt2],     ah[mt], ble);
                    mma_bf16(acc[mt][2 * nt2],     al[mt], bhe);
                    mma_bf16(acc[mt][2 * nt2 + 1], ah[mt], bho);
                    mma_bf16(acc[mt][2 * nt2 + 1], ah[mt], blo);
                    mma_bf16(acc[mt][2 * nt2 + 1], al[mt], bho);
                }
            }
        }
        __syncthreads();
    }

    // epilogue
#pragma unroll
    for (int mt = 0; mt < 2; mt++) {
#pragma unroll
        for (int nt = 0; nt < 8; nt++) {
            const int row = m0 + wm * 32 + mt * 16 + gg;
            const int col = n0 + wn * 64 + nt * 8 + 2 * tt;
            float2 v0 = make_float2(acc[mt][nt][0], acc[mt][nt][1]);
            float2 v1 = make_float2(acc[mt][nt][2], acc[mt][nt][3]);
            if (bias) {
                v0.x += bias[col]; v0.y += bias[col + 1];
                v1.x += bias[col]; v1.y += bias[col + 1];
            }
            *(float2*)(Cm + (size_t)row * Ndim + col)       = v0;
            *(float2*)(Cm + (size_t)(row + 8) * Ndim + col) = v1;
        }
    }
}

// ---------------- fp32 -> bf16 hi/lo split ---------------------------------
__global__ void split_kernel(const float* __restrict__ src,
                             __nv_bfloat16* __restrict__ hi,
                             __nv_bfloat16* __restrict__ lo, int n)
{
    int i = blockIdx.x * blockDim.x + threadIdx.x;
    if (i >= n) return;
    float a = src[i];
    __nv_bfloat16 h = __float2bfloat16(a);
    hi[i] = h;
    lo[i] = __float2bfloat16(a - __bfloat162float(h));
}

// ---------------- transpose + split: W[K,N] -> Wt_hi/lo[N,K] ---------------
__global__ void transpose_split_kernel(const float* __restrict__ W,
                                       __nv_bfloat16* __restrict__ Th,
                                       __nv_bfloat16* __restrict__ Tl,
                                       int Kdim, int Ndim)
{
    __shared__ float t[32][33];
    const int n0 = blockIdx.x * 32, k0 = blockIdx.y * 32;
    const int tx = threadIdx.x, ty = threadIdx.y;
#pragma unroll
    for (int j = 0; j < 32; j += 8)
        t[ty + j][tx] = W[(size_t)(k0 + ty + j) * Ndim + n0 + tx];
    __syncthreads();
#pragma unroll
    for (int j = 0; j < 32; j += 8) {
        float a = t[tx][ty + j];
        __nv_bfloat16 h = __float2bfloat16(a);
        size_t o = (size_t)(n0 + ty + j) * Kdim + k0 + tx;
        Th[o] = h;
        Tl[o] = __float2bfloat16(a - __bfloat162float(h));
    }
}

// ---------------- RoPE ------------------------------------------------------
__global__ void rope_kernel(float* __restrict__ p, int nh, int total)
{
    int idx = blockIdx.x * blockDim.x + threadIdx.x;
    if (idx >= total) return;
    const int d2  = idx & 63;
    const int h   = (idx >> 6) % nh;
    const int row = idx / (64 * nh);
    const int t   = row % T_;

    const float inv_freq = powf(10000.0f, -(float)d2 / 64.0f);
    float s, c;
    sincosf((float)t * inv_freq, &s, &c);

    const size_t off = (size_t)row * nh * D_ + (size_t)h * D_ + 2 * d2;
    const float xr = p[off], xi = p[off + 1];
    p[off]     = xr * c - xi * s;
    p[off + 1] = xr * s + xi * c;
}

// ---------------------------------------------------------------------------
// Causal GQA attention. BQ=16 queries/block, 512 threads (warp w = query w).
// Phase 1: lane-per-score (no shuffles), K tile padded stride 132 floats.
// smem = sc[16*1024] + kv[32*132] + sq[16*128] floats = 90624 B.
// ---------------------------------------------------------------------------
#define BQ 16
#define SK 32
#define KVP 132

__global__ __launch_bounds__(512)
void attn_kernel(const float* __restrict__ q, const float* __restrict__ k,
                 const float* __restrict__ v, float* __restrict__ out)
{
    extern __shared__ float smf[];
    float* sc = smf;                    // [BQ][T_]
    float* kv = smf + BQ * T_;          // [SK][KVP]
    float* sq = kv + SK * KVP;          // [BQ][D_]

    const int tq  = blockIdx.x;
    const int h   = blockIdx.y;
    const int b   = blockIdx.z;
    const int g   = h >> 2;             // 4 q-heads per kv group
    const int tid = threadIdx.x;
    const int lane = tid & 31;
    const int w    = tid >> 5;          // 0..15: query row in tile

    const int base = tq * BQ;
    const int tQ   = base + w;
    const int Smax = base + BQ;
    const int Send = ((Smax + SK - 1) / SK) * SK;
    const float scale = 0.08838834764831845f;   // 1/sqrt(128)

    // stage q rows into smem
    for (int i = tid; i < BQ * D_; i += 512) {
        const int r = i >> 7, d = i & 127;
        sq[i] = q[(((size_t)b * T_ + base + r) * H_ + h) * D_ + d];
    }

    // ---- Phase 1: scores (lane-per-s, no shuffles) ----
    for (int s0 = 0; s0 < Smax; s0 += SK) {
        __syncthreads();
        for (int i = tid; i < SK * 32; i += 512) {     // 32 rows x 32 float4
            const int r = i >> 5, c4 = (i & 31) * 4;
            const float* kr = k + (((size_t)b * T_ + (s0 + r)) * G_ + g) * D_;
            *(float4*)(kv + r * KVP + c4) = *(const float4*)(kr + c4);
        }
        __syncthreads();

        const int s = s0 + lane;
        const float* kr = kv + lane * KVP;
        const float* qr = sq + w * D_;
        float p = 0.f;
#pragma unroll 8
        for (int dq = 0; dq < 32; dq++) {
            const float4 kx = ((const float4*)kr)[dq];
            const float4 qx = ((const float4*)qr)[dq];
            p = fmaf(kx.x, qx.x, p);
            p = fmaf(kx.y, qx.y, p);
            p = fmaf(kx.z, qx.z, p);
            p = fmaf(kx.w, qx.w, p);
        }
        sc[w * T_ + s] = (s <= tQ) ? p * scale : -1e30f;
    }
    __syncthreads();

    for (int s = Smax + lane; s < Send; s += 32) sc[w * T_ + s] = -1e30f;
    __syncwarp();

    // ---- Phase 2: softmax over own row (per warp) ----
    float m = -1e30f;
    for (int s = lane; s < Send; s += 32) m = fmaxf(m, sc[w * T_ + s]);
#pragma unroll
    for (int o = 16; o; o >>= 1) m = fmaxf(m, __shfl_xor_sync(0xffffffffu, m, o));
    float lsum = 0.f;
    for (int s = lane; s < Send; s += 32) {
        const float e = __expf(sc[w * T_ + s] - m);
        sc[w * T_ + s] = e;
        lsum += e;
    }
#pragma unroll
    for (int o = 16; o; o >>= 1) lsum += __shfl_xor_sync(0xffffffffu, lsum, o);
    const float inv = 1.0f / lsum;

    // ---- Phase 3: probs @ V ----
    float a0 = 0.f, a1 = 0.f, a2 = 0.f, a3 = 0.f;
    for (int s0 = 0; s0 < Smax; s0 += SK) {
        __syncthreads();
        for (int i = tid; i < SK * 32; i += 512) {
            const int r = i >> 5, c4 = (i & 31) * 4;
            const float* vr = v + (((size_t)b * T_ + (s0 + r)) * G_ + g) * D_;
            *(float4*)(kv + r * KVP + c4) = *(const float4*)(vr + c4);
        }
        __syncthreads();
        const float* scrow = sc + w * T_ + s0;
#pragma unroll 8
        for (int si = 0; si < SK; si++) {
            const float p = scrow[si];
            const float* vrow = kv + si * KVP;
            a0 = fmaf(p, vrow[lane],      a0);
            a1 = fmaf(p, vrow[lane + 32], a1);
            a2 = fmaf(p, vrow[lane + 64], a2);
            a3 = fmaf(p, vrow[lane + 96], a3);
        }
    }

    const size_t o = (((size_t)b * T_ + tQ) * H_ + h) * D_;
    out[o + lane]      = a0 * inv;
    out[o + lane + 32] = a1 * inv;
    out[o + lane + 64] = a2 * inv;
    out[o + lane + 96] = a3 * inv;
}

// ---------------------------------------------------------------------------
extern "C" void kernel_launch(void* const* d_in, const int* in_sizes, int n_in,
                              void* d_out, int out_size)
{
    const float* x  = (const float*)d_in[0];
    const float* Wq = (const float*)d_in[1];
    const float* Wk = (const float*)d_in[2];
    const float* Wv = (const float*)d_in[3];
    const float* Wo = (const float*)d_in[4];
    const float* bo = (const float*)d_in[5];
    float* out = (float*)d_out;

    float *q, *k, *v, *att;
    __nv_bfloat16 *xh, *xl, *ath, *atl;
    __nv_bfloat16 *wqh, *wql, *wkh, *wkl, *wvh, *wvl, *woh, *wol;
    cudaGetSymbolAddress((void**)&q,   g_q);
    cudaGetSymbolAddress((void**)&k,   g_k);
    cudaGetSymbolAddress((void**)&v,   g_v);
    cudaGetSymbolAddress((void**)&att, g_att);
    cudaGetSymbolAddress((void**)&xh,  g_xh);
    cudaGetSymbolAddress((void**)&xl,  g_xl);
    cudaGetSymbolAddress((void**)&ath, g_ath);
    cudaGetSymbolAddress((void**)&atl, g_atl);
    cudaGetSymbolAddress((void**)&wqh, g_wqh);
    cudaGetSymbolAddress((void**)&wql, g_wql);
    cudaGetSymbolAddress((void**)&wkh, g_wkh);
    cudaGetSymbolAddress((void**)&wkl, g_wkl);
    cudaGetSymbolAddress((void**)&wvh, g_wvh);
    cudaGetSymbolAddress((void**)&wvl, g_wvl);
    cudaGetSymbolAddress((void**)&woh, g_woh);
    cudaGetSymbolAddress((void**)&wol, g_wol);

    cudaFuncSetAttribute(gemm_mma_kernel,
                         cudaFuncAttributeMaxDynamicSharedMemorySize, GEMM_SMEM);

    // convert inputs
    split_kernel<<<(M_ * C_ + 255) / 256, 256>>>(x, xh, xl, M_ * C_);
    transpose_split_kernel<<<dim3(H_ * D_ / 32, C_ / 32), dim3(32, 8)>>>(Wq, wqh, wql, C_, H_ * D_);
    transpose_split_kernel<<<dim3(G_ * D_ / 32, C_ / 32), dim3(32, 8)>>>(Wk, wkh, wkl, C_, G_ * D_);
    transpose_split_kernel<<<dim3(G_ * D_ / 32, C_ / 32), dim3(32, 8)>>>(Wv, wvh, wvl, C_, G_ * D_);
    transpose_split_kernel<<<dim3(C_ / 32, (H_ * D_) / 32), dim3(32, 8)>>>(Wo, woh, wol, H_ * D_, C_);

    // Q projection
    gemm_mma_kernel<<<dim3((H_ * D_) / 128, M_ / 128, 1), 256, GEMM_SMEM>>>(
        xh, xl, wqh, wql, wqh, wql, nullptr, q, q, H_ * D_, C_);
    // fused K + V projections
    gemm_mma_kernel<<<dim3((G_ * D_) / 128, M_ / 128, 2), 256, GEMM_SMEM>>>(
        xh, xl, wkh, wkl, wvh, wvl, nullptr, k, v, G_ * D_, C_);

    // RoPE
    rope_kernel<<<(M_ * H_ * 64 + 255) / 256, 256>>>(q, H_, M_ * H_ * 64);
    rope_kernel<<<(M_ * G_ * 64 + 255) / 256, 256>>>(k, G_, M_ * G_ * 64);

    // Attention
    {
        const int smem = (BQ * T_ + SK * KVP + BQ * D_) * (int)sizeof(float);   // 90624
        cudaFuncSetAttribute(attn_kernel,
                             cudaFuncAttributeMaxDynamicSharedMemorySize, smem);
        attn_kernel<<<dim3(T_ / BQ, H_, B_), 512, smem>>>(q, k, v, att);
    }

    // Output projection + bias
    split_kernel<<<(M_ * C_ + 255) / 256, 256>>>(att, ath, atl, M_ * C_);
    gemm_mma_kernel<<<dim3(C_ / 128, M_ / 128, 1), 256, GEMM_SMEM>>>(
        ath, atl, woh, wol, woh, wol, bo, out, out, C_, H_ * D_);
}

// round 7
// speedup vs baseline: 3.7604x; 1.5856x over previous
#include <cuda_runtime.h>
#include <cuda_bf16.h>
#include <math.h>
#include <stdint.h>

#define B_  2
#define T_  1024
#define C_  4096
#define H_  32
#define G_  8
#define D_  128
#define M_  (B_*T_)          // 2048 rows

// ---------------- scratch (__device__ globals; no allocs allowed) ----------
__device__ float g_q  [M_ * H_ * D_];
__device__ float g_k  [M_ * G_ * D_];
__device__ float g_v  [M_ * G_ * D_];

__device__ __nv_bfloat16 g_xh [M_ * C_];
__device__ __nv_bfloat16 g_xl [M_ * C_];
__device__ __nv_bfloat16 g_ath[M_ * C_];
__device__ __nv_bfloat16 g_atl[M_ * C_];
__device__ __nv_bfloat16 g_qh [M_ * H_ * D_];
__device__ __nv_bfloat16 g_ql [M_ * H_ * D_];
__device__ __nv_bfloat16 g_kh [M_ * G_ * D_];
__device__ __nv_bfloat16 g_kl [M_ * G_ * D_];
__device__ __nv_bfloat16 g_vh [M_ * G_ * D_];
__device__ __nv_bfloat16 g_vl [M_ * G_ * D_];
// transposed weights, [N, K] K-major, bf16 hi/lo
__device__ __nv_bfloat16 g_wqh[(H_*D_) * C_];
__device__ __nv_bfloat16 g_wql[(H_*D_) * C_];
__device__ __nv_bfloat16 g_wkh[(G_*D_) * C_];
__device__ __nv_bfloat16 g_wkl[(G_*D_) * C_];
__device__ __nv_bfloat16 g_wvh[(G_*D_) * C_];
__device__ __nv_bfloat16 g_wvl[(G_*D_) * C_];
__device__ __nv_bfloat16 g_woh[C_ * (H_*D_)];
__device__ __nv_bfloat16 g_wol[C_ * (H_*D_)];

// ---------------- helpers ---------------------------------------------------
__device__ __forceinline__ uint32_t smem_u32(const void* p) {
    uint32_t a;
    asm("{ .reg .u64 t; cvta.to.shared.u64 t, %1; cvt.u32.u64 %0, t; }"
        : "=r"(a) : "l"(p));
    return a;
}
__device__ __forceinline__ void cp16(uint32_t dst, const void* src) {
    asm volatile("cp.async.cg.shared.global [%0], [%1], 16;"
                 :: "r"(dst), "l"(src) : "memory");
}
__device__ __forceinline__ void cp_commit() {
    asm volatile("cp.async.commit_group;" ::: "memory");
}
template <int N>
__device__ __forceinline__ void cp_wait() {
    asm volatile("cp.async.wait_group %0;" :: "n"(N) : "memory");
}
__device__ __forceinline__ void mma_bf16(float* c, const uint32_t* a, const uint32_t* b) {
    asm volatile(
        "mma.sync.aligned.m16n8k16.row.col.f32.bf16.bf16.f32 "
        "{%0,%1,%2,%3}, {%4,%5,%6,%7}, {%8,%9}, {%0,%1,%2,%3};"
        : "+f"(c[0]), "+f"(c[1]), "+f"(c[2]), "+f"(c[3])
        : "r"(a[0]), "r"(a[1]), "r"(a[2]), "r"(a[3]), "r"(b[0]), "r"(b[1]));
}
__device__ __forceinline__ void ldsm4(uint32_t* r, uint32_t a) {
    asm volatile("ldmatrix.sync.aligned.m8n8.x4.shared.b16 {%0,%1,%2,%3}, [%4];"
        : "=r"(r[0]), "=r"(r[1]), "=r"(r[2]), "=r"(r[3]) : "r"(a));
}
__device__ __forceinline__ void ldsm4t(uint32_t* r, uint32_t a) {
    asm volatile("ldmatrix.sync.aligned.m8n8.x4.trans.shared.b16 {%0,%1,%2,%3}, [%4];"
        : "=r"(r[0]), "=r"(r[1]), "=r"(r[2]), "=r"(r[3]) : "r"(a));
}
__device__ __forceinline__ uint32_t packbf(float a, float b) {
    __nv_bfloat162 t;
    t.x = __float2bfloat16(a);
    t.y = __float2bfloat16(b);
    return *(uint32_t*)&t;
}

// ---------------------------------------------------------------------------
// bf16x3 HMMA GEMM (unchanged from R5): C = A @ Wt^T (+bias).
// ---------------------------------------------------------------------------
#define SA 40
#define MAT_BYTES (128 * SA * 2)
#define STAGE_BYTES (4 * MAT_BYTES)
#define GEMM_SMEM (2 * STAGE_BYTES)

__global__ __launch_bounds__(256, 2)
void gemm_mma_kernel(const __nv_bfloat16* __restrict__ Ah, const __nv_bfloat16* __restrict__ Al,
                     const __nv_bfloat16* __restrict__ B1h, const __nv_bfloat16* __restrict__ B1l,
                     const __nv_bfloat16* __restrict__ B2h, const __nv_bfloat16* __restrict__ B2l,
                     const float* __restrict__ bias,
                     float* __restrict__ C1, float* __restrict__ C2,
                     int Ndim, int Kdim)
{
    extern __shared__ char sm[];
    const uint32_t smb = smem_u32(sm);
    const int tid  = threadIdx.x;
    const int lane = tid & 31;
    const int w    = tid >> 5;
    const int wm   = w & 3;
    const int wn   = w >> 2;
    const int gg   = lane >> 2;
    const int tt   = lane & 3;
    const int m0   = blockIdx.y * 128;
    const int n0   = blockIdx.x * 128;

    const __nv_bfloat16* Bh = blockIdx.z ? B2h : B1h;
    const __nv_bfloat16* Bl = blockIdx.z ? B2l : B1l;
    float* Cm = blockIdx.z ? C2 : C1;

    const int nchunks = Kdim >> 5;
    const __nv_bfloat16* gsrc[4] = { Ah, Al, Bh, Bl };

    auto issue_stage = [&](int c, int st) {
        const int k0 = c << 5;
#pragma unroll
        for (int j = 0; j < 8; j++) {
            const int mat = j >> 1;
            const int idx = tid + ((j & 1) << 8);
            const int r   = idx >> 2;
            const int s   = idx & 3;
            const int grow = (mat < 2) ? (m0 + r) : (n0 + r);
            const __nv_bfloat16* src = gsrc[mat] + (size_t)grow * Kdim + k0 + s * 8;
            const uint32_t dst = smb + st * STAGE_BYTES + mat * MAT_BYTES + r * (SA * 2) + s * 16;
            cp16(dst, src);
        }
        cp_commit();
    };

    float acc[2][8][4];
#pragma unroll
    for (int i = 0; i < 2; i++)
#pragma unroll
        for (int j = 0; j < 8; j++)
#pragma unroll
            for (int l = 0; l < 4; l++) acc[i][j][l] = 0.f;

    const uint32_t aoff0 = (uint32_t)((wm * 32 + (lane & 7) + ((lane >> 3) & 1) * 8) * (SA * 2)
                                      + ((lane >> 4) & 1) * 16);
    const uint32_t boff0 = (uint32_t)((wn * 64 + (lane & 7) + ((lane >> 3) & 1) * 8) * (SA * 2)
                                      + ((lane >> 4) & 1) * 16);

    issue_stage(0, 0);

    for (int c = 0; c < nchunks; ++c) {
        const int st = c & 1;
        if (c + 1 < nchunks) { issue_stage(c + 1, st ^ 1); cp_wait<1>(); }
        else                 { cp_wait<0>(); }
        __syncthreads();

        const uint32_t sAh = smb + st * STAGE_BYTES;
        const uint32_t sAl = sAh + MAT_BYTES;
        const uint32_t sBh = sAh + 2 * MAT_BYTES;
        const uint32_t sBl = sAh + 3 * MAT_BYTES;

#pragma unroll
        for (int k16 = 0; k16 < 32; k16 += 16) {
            uint32_t ah[2][4], al[2][4];
#pragma unroll
            for (int mt = 0; mt < 2; mt++) {
                const uint32_t ao = aoff0 + mt * 16 * (SA * 2) + k16 * 2;
                ldsm4(ah[mt], sAh + ao);
                ldsm4(al[mt], sAl + ao);
            }
#pragma unroll
            for (int nt2 = 0; nt2 < 4; nt2++) {
                const uint32_t bo = boff0 + nt2 * 16 * (SA * 2) + k16 * 2;
                uint32_t bh4[4], bl4[4];
                ldsm4(bh4, sBh + bo);
                ldsm4(bl4, sBl + bo);
                uint32_t bhe[2] = { bh4[0], bh4[2] }, bho[2] = { bh4[1], bh4[3] };
                uint32_t ble[2] = { bl4[0], bl4[2] }, blo[2] = { bl4[1], bl4[3] };
#pragma unroll
                for (int mt = 0; mt < 2; mt++) {
                    mma_bf16(acc[mt][2 * nt2],     ah[mt], bhe);
                    mma_bf16(acc[mt][2 * nt2],     ah[mt], ble);
                    mma_bf16(acc[mt][2 * nt2],     al[mt], bhe);
                    mma_bf16(acc[mt][2 * nt2 + 1], ah[mt], bho);
                    mma_bf16(acc[mt][2 * nt2 + 1], ah[mt], blo);
                    mma_bf16(acc[mt][2 * nt2 + 1], al[mt], bho);
                }
            }
        }
        __syncthreads();
    }

#pragma unroll
    for (int mt = 0; mt < 2; mt++) {
#pragma unroll
        for (int nt = 0; nt < 8; nt++) {
            const int row = m0 + wm * 32 + mt * 16 + gg;
            const int col = n0 + wn * 64 + nt * 8 + 2 * tt;
            float2 v0 = make_float2(acc[mt][nt][0], acc[mt][nt][1]);
            float2 v1 = make_float2(acc[mt][nt][2], acc[mt][nt][3]);
            if (bias) {
                v0.x += bias[col]; v0.y += bias[col + 1];
                v1.x += bias[col]; v1.y += bias[col + 1];
            }
            *(float2*)(Cm + (size_t)row * Ndim + col)       = v0;
            *(float2*)(Cm + (size_t)(row + 8) * Ndim + col) = v1;
        }
    }
}

// ---------------- fp32 -> bf16 hi/lo split (optional scale) ----------------
__global__ void split_kernel(const float* __restrict__ src,
                             __nv_bfloat16* __restrict__ hi,
                             __nv_bfloat16* __restrict__ lo, int n, float scale)
{
    int i = blockIdx.x * blockDim.x + threadIdx.x;
    if (i >= n) return;
    float a = src[i] * scale;
    __nv_bfloat16 h = __float2bfloat16(a);
    hi[i] = h;
    lo[i] = __float2bfloat16(a - __bfloat162float(h));
}

// ---------------- transpose + split: W[K,N] -> Wt_hi/lo[N,K] ---------------
__global__ void transpose_split_kernel(const float* __restrict__ W,
                                       __nv_bfloat16* __restrict__ Th,
                                       __nv_bfloat16* __restrict__ Tl,
                                       int Kdim, int Ndim)
{
    __shared__ float t[32][33];
    const int n0 = blockIdx.x * 32, k0 = blockIdx.y * 32;
    const int tx = threadIdx.x, ty = threadIdx.y;
#pragma unroll
    for (int j = 0; j < 32; j += 8)
        t[ty + j][tx] = W[(size_t)(k0 + ty + j) * Ndim + n0 + tx];
    __syncthreads();
#pragma unroll
    for (int j = 0; j < 32; j += 8) {
        float a = t[tx][ty + j];
        __nv_bfloat16 h = __float2bfloat16(a);
        size_t o = (size_t)(n0 + ty + j) * Kdim + k0 + tx;
        Th[o] = h;
        Tl[o] = __float2bfloat16(a - __bfloat162float(h));
    }
}

// ---------------- RoPE ------------------------------------------------------
__global__ void rope_kernel(float* __restrict__ p, int nh, int total)
{
    int idx = blockIdx.x * blockDim.x + threadIdx.x;
    if (idx >= total) return;
    const int d2  = idx & 63;
    const int h   = (idx >> 6) % nh;
    const int row = idx / (64 * nh);
    const int t   = row % T_;

    const float inv_freq = powf(10000.0f, -(float)d2 / 64.0f);
    float s, c;
    sincosf((float)t * inv_freq, &s, &c);

    const size_t off = (size_t)row * nh * D_ + (size_t)h * D_ + 2 * d2;
    const float xr = p[off], xi = p[off + 1];
    p[off]     = xr * c - xi * s;
    p[off + 1] = xr * s + xi * c;
}

// ---------------------------------------------------------------------------
// Flash attention, bf16x3 HMMA. CTA = 64 queries x 1 head; 4 warps (16 q each).
// K/V streamed in 64-key chunks (hi/lo bf16, 272B padded rows). Online softmax
// in fp32. Causal: tq+1 chunks. Output written directly as bf16 hi/lo.
// ---------------------------------------------------------------------------
#define FA_ROW 272                    // 136 bf16 per row
#define FA_MAT (64 * FA_ROW)          // 17408 B
#define FA_SMEM (6 * FA_MAT)          // 104448 B

__global__ __launch_bounds__(128, 2)
void flash_attn_kernel(const __nv_bfloat16* __restrict__ qh, const __nv_bfloat16* __restrict__ ql,
                       const __nv_bfloat16* __restrict__ kh, const __nv_bfloat16* __restrict__ kl,
                       const __nv_bfloat16* __restrict__ vh, const __nv_bfloat16* __restrict__ vl,
                       __nv_bfloat16* __restrict__ oh, __nv_bfloat16* __restrict__ ol)
{
    extern __shared__ char sm[];
    const uint32_t smb = smem_u32(sm);
    const uint32_t sQh = smb,            sQl = smb + FA_MAT;
    const uint32_t sKh = smb + 2*FA_MAT, sKl = smb + 3*FA_MAT;
    const uint32_t sVh = smb + 4*FA_MAT, sVl = smb + 5*FA_MAT;
    const int tid = threadIdx.x, lane = tid & 31, w = tid >> 5;
    const int gg = lane >> 2, tt = lane & 3;
    const int tq = blockIdx.x, h = blockIdx.y, b = blockIdx.z, g = h >> 2;
    const int qbase = tq * 64;

    // ldmatrix per-lane offset pattern (row, col-block) shared by Q/K/V tiles
    const uint32_t lrow = (lane & 7) + ((lane >> 3) & 1) * 8;
    const uint32_t lcol16 = ((lane >> 4) & 1) * 16;        // bytes

    // ---- Q load (group 0) ----
#pragma unroll
    for (int j = 0; j < 16; j++) {
        const int i = tid + j * 128;
        const int matlo = i >> 10, idx = i & 1023, r = idx >> 4, s = idx & 15;
        const __nv_bfloat16* src = (matlo ? ql : qh)
            + (((size_t)b * T_ + qbase + r) * H_ + h) * D_ + s * 8;
        cp16((matlo ? sQl : sQh) + r * FA_ROW + s * 16, src);
    }
    cp_commit();

    auto loadK = [&](int s0) {
#pragma unroll
        for (int j = 0; j < 16; j++) {
            const int i = tid + j * 128;
            const int matlo = i >> 10, idx = i & 1023, r = idx >> 4, s = idx & 15;
            const __nv_bfloat16* src = (matlo ? kl : kh)
                + (((size_t)b * T_ + s0 + r) * G_ + g) * D_ + s * 8;
            cp16((matlo ? sKl : sKh) + r * FA_ROW + s * 16, src);
        }
        cp_commit();
    };
    auto loadV = [&](int s0) {
#pragma unroll
        for (int j = 0; j < 16; j++) {
            const int i = tid + j * 128;
            const int matlo = i >> 10, idx = i & 1023, r = idx >> 4, s = idx & 15;
            const __nv_bfloat16* src = (matlo ? vl : vh)
                + (((size_t)b * T_ + s0 + r) * G_ + g) * D_ + s * 8;
            cp16((matlo ? sVl : sVh) + r * FA_ROW + s * 16, src);
        }
        cp_commit();
    };

    loadK(0);            // group 1
    loadV(0);            // group 2
    cp_wait<1>();        // Q + K0 arrived
    __syncthreads();

    // ---- preload Q fragments (regs; sQ never overwritten) ----
    uint32_t qfh[8][4], qfl[8][4];
    const uint32_t qoff = (w * 16 + lrow) * FA_ROW + lcol16;
#pragma unroll
    for (int k16 = 0; k16 < 8; k16++) {
        ldsm4(qfh[k16], sQh + qoff + k16 * 32);
        ldsm4(qfl[k16], sQl + qoff + k16 * 32);
    }

    float O[16][4];
#pragma unroll
    for (int i = 0; i < 16; i++)
#pragma unroll
        for (int j = 0; j < 4; j++) O[i][j] = 0.f;
    float mrow[2] = { -1e30f, -1e30f }, lrow_s[2] = { 0.f, 0.f };

    const int nch = tq + 1;
    for (int c = 0; c < nch; c++) {
        const int s0 = c * 64;

        // ---- S = Q @ K^T (bf16x3) ----
        float S[8][4];
#pragma unroll
        for (int i = 0; i < 8; i++)
#pragma unroll
            for (int j = 0; j < 4; j++) S[i][j] = 0.f;

#pragma unroll
        for (int k16 = 0; k16 < 8; k16++) {
#pragma unroll
            for (int nt2 = 0; nt2 < 4; nt2++) {
                const uint32_t bo = (nt2 * 16 + lrow) * FA_ROW + k16 * 32 + lcol16;
                uint32_t bh4[4], bl4[4];
                ldsm4(bh4, sKh + bo);
                ldsm4(bl4, sKl + bo);
                uint32_t bhe[2] = { bh4[0], bh4[2] }, bho[2] = { bh4[1], bh4[3] };
                uint32_t ble[2] = { bl4[0], bl4[2] }, blo[2] = { bl4[1], bl4[3] };
                mma_bf16(S[2 * nt2],     qfh[k16], bhe);
                mma_bf16(S[2 * nt2],     qfh[k16], ble);
                mma_bf16(S[2 * nt2],     qfl[k16], bhe);
                mma_bf16(S[2 * nt2 + 1], qfh[k16], bho);
                mma_bf16(S[2 * nt2 + 1], qfh[k16], blo);
                mma_bf16(S[2 * nt2 + 1], qfl[k16], bho);
            }
        }

        // ---- causal mask (diagonal chunk only) ----
        if (c == tq) {
#pragma unroll
            for (int nt = 0; nt < 8; nt++)
#pragma unroll
                for (int ci = 0; ci < 4; ci++) {
                    const int s = s0 + nt * 8 + 2 * tt + (ci & 1);
                    const int qr = qbase + w * 16 + gg + 8 * (ci >> 1);
                    if (s > qr) S[nt][ci] = -1e30f;
                }
        }

        // ---- online softmax ----
        float mnew[2];
#pragma unroll
        for (int r = 0; r < 2; r++) {
            float mx = mrow[r];
#pragma unroll
            for (int nt = 0; nt < 8; nt++)
                mx = fmaxf(mx, fmaxf(S[nt][2 * r], S[nt][2 * r + 1]));
            mx = fmaxf(mx, __shfl_xor_sync(0xffffffffu, mx, 1));
            mx = fmaxf(mx, __shfl_xor_sync(0xffffffffu, mx, 2));
            mnew[r] = mx;
            const float alpha = __expf(mrow[r] - mx);
            lrow_s[r] *= alpha;
            mrow[r] = mx;
#pragma unroll
            for (int dt = 0; dt < 16; dt++) {
                O[dt][2 * r]     *= alpha;
                O[dt][2 * r + 1] *= alpha;
            }
        }

        // ---- exp + pack P (hi/lo) ----
        uint32_t Ph[4][4], Pl[4][4];
        float sum0 = 0.f, sum1 = 0.f;
#pragma unroll
        for (int ci16 = 0; ci16 < 4; ci16++) {
#pragma unroll
            for (int half = 0; half < 2; half++) {        // tiles 2*ci16, 2*ci16+1
                const int nt = 2 * ci16 + half;
                float p0 = __expf(S[nt][0] - mnew[0]);
                float p1 = __expf(S[nt][1] - mnew[0]);
                float p2 = __expf(S[nt][2] - mnew[1]);
                float p3 = __expf(S[nt][3] - mnew[1]);
                sum0 += p0 + p1;
                sum1 += p2 + p3;
                float h0 = __bfloat162float(__float2bfloat16(p0));
                float h1 = __bfloat162float(__float2bfloat16(p1));
                float h2 = __bfloat162float(__float2bfloat16(p2));
                float h3 = __bfloat162float(__float2bfloat16(p3));
                Ph[ci16][0 + 2 * half] = packbf(h0, h1);
                Ph[ci16][1 + 2 * half] = packbf(h2, h3);
                Pl[ci16][0 + 2 * half] = packbf(p0 - h0, p1 - h1);
                Pl[ci16][1 + 2 * half] = packbf(p2 - h2, p3 - h3);
            }
            // reorder: a-frag wants (a0,a1)=tile even rows gg/gg+8, (a2,a3)=tile odd
            // built as [0]=even(gg),[1]=even(gg+8),[2]=odd(gg),[3]=odd(gg+8) — correct.
        }
        sum0 += __shfl_xor_sync(0xffffffffu, sum0, 1);
        sum0 += __shfl_xor_sync(0xffffffffu, sum0, 2);
        sum1 += __shfl_xor_sync(0xffffffffu, sum1, 1);
        sum1 += __shfl_xor_sync(0xffffffffu, sum1, 2);
        lrow_s[0] += sum0;
        lrow_s[1] += sum1;

        // ---- prefetch K(c+1); wait for V(c) ----
        __syncthreads();                       // all warps done with K smem
        if (c + 1 < nch) { loadK(s0 + 64); cp_wait<1>(); }
        else             { cp_wait<0>(); }
        __syncthreads();                       // V(c) visible

        // ---- O += P @ V (bf16x3) ----
#pragma unroll
        for (int dt2 = 0; dt2 < 8; dt2++) {
#pragma unroll
            for (int ci16 = 0; ci16 < 4; ci16++) {
                const uint32_t vo = (ci16 * 16 + lrow) * FA_ROW + dt2 * 32 + lcol16;
                uint32_t vfh[4], vfl[4];
                ldsm4t(vfh, sVh + vo);
                ldsm4t(vfl, sVl + vo);
                uint32_t vhe[2] = { vfh[0], vfh[1] }, vho[2] = { vfh[2], vfh[3] };
                uint32_t vle[2] = { vfl[0], vfl[1] }, vlo[2] = { vfl[2], vfl[3] };
                mma_bf16(O[2 * dt2],     Ph[ci16], vhe);
                mma_bf16(O[2 * dt2],     Pl[ci16], vhe);
                mma_bf16(O[2 * dt2],     Ph[ci16], vle);
                mma_bf16(O[2 * dt2 + 1], Ph[ci16], vho);
                mma_bf16(O[2 * dt2 + 1], Pl[ci16], vho);
                mma_bf16(O[2 * dt2 + 1], Ph[ci16], vlo);
            }
        }

        // ---- prefetch V(c+1) ----
        __syncthreads();                       // all warps done with V smem
        if (c + 1 < nch) {
            loadV(s0 + 64);
            cp_wait<1>();                      // K(c+1) ready (V(c+1) newest may pend)
            __syncthreads();
        }
    }

    // ---- epilogue: normalize + split to bf16 hi/lo ----
    const float inv0 = 1.f / lrow_s[0], inv1 = 1.f / lrow_s[1];
    const int q0 = qbase + w * 16 + gg;
#pragma unroll
    for (int dt = 0; dt < 16; dt++) {
        const int col = dt * 8 + 2 * tt;
        const size_t o0 = (((size_t)b * T_ + q0) * H_ + h) * D_ + col;
        const size_t o1 = (((size_t)b * T_ + q0 + 8) * H_ + h) * D_ + col;
        float a0 = O[dt][0] * inv0, a1 = O[dt][1] * inv0;
        float a2 = O[dt][2] * inv1, a3 = O[dt][3] * inv1;
        float h0 = __bfloat162float(__float2bfloat16(a0));
        float h1 = __bfloat162float(__float2bfloat16(a1));
        float h2 = __bfloat162float(__float2bfloat16(a2));
        float h3 = __bfloat162float(__float2bfloat16(a3));
        *(uint32_t*)(oh + o0) = packbf(h0, h1);
        *(uint32_t*)(oh + o1) = packbf(h2, h3);
        *(uint32_t*)(ol + o0) = packbf(a0 - h0, a1 - h1);
        *(uint32_t*)(ol + o1) = packbf(a2 - h2, a3 - h3);
    }
}

// ---------------------------------------------------------------------------
extern "C" void kernel_launch(void* const* d_in, const int* in_sizes, int n_in,
                              void* d_out, int out_size)
{
    const float* x  = (const float*)d_in[0];
    const float* Wq = (const float*)d_in[1];
    const float* Wk = (const float*)d_in[2];
    const float* Wv = (const float*)d_in[3];
    const float* Wo = (const float*)d_in[4];
    const float* bo = (const float*)d_in[5];
    float* out = (float*)d_out;

    float *q, *k, *v;
    __nv_bfloat16 *xh, *xl, *ath, *atl, *qh, *ql, *kh, *kl, *vh, *vl;
    __nv_bfloat16 *wqh, *wql, *wkh, *wkl, *wvh, *wvl, *woh, *wol;
    cudaGetSymbolAddress((void**)&q,   g_q);
    cudaGetSymbolAddress((void**)&k,   g_k);
    cudaGetSymbolAddress((void**)&v,   g_v);
    cudaGetSymbolAddress((void**)&xh,  g_xh);
    cudaGetSymbolAddress((void**)&xl,  g_xl);
    cudaGetSymbolAddress((void**)&ath, g_ath);
    cudaGetSymbolAddress((void**)&atl, g_atl);
    cudaGetSymbolAddress((void**)&qh,  g_qh);
    cudaGetSymbolAddress((void**)&ql,  g_ql);
    cudaGetSymbolAddress((void**)&kh,  g_kh);
    cudaGetSymbolAddress((void**)&kl,  g_kl);
    cudaGetSymbolAddress((void**)&vh,  g_vh);
    cudaGetSymbolAddress((void**)&vl,  g_vl);
    cudaGetSymbolAddress((void**)&wqh, g_wqh);
    cudaGetSymbolAddress((void**)&wql, g_wql);
    cudaGetSymbolAddress((void**)&wkh, g_wkh);
    cudaGetSymbolAddress((void**)&wkl, g_wkl);
    cudaGetSymbolAddress((void**)&wvh, g_wvh);
    cudaGetSymbolAddress((void**)&wvl, g_wvl);
    cudaGetSymbolAddress((void**)&woh, g_woh);
    cudaGetSymbolAddress((void**)&wol, g_wol);

    cudaFuncSetAttribute(gemm_mma_kernel,
                         cudaFuncAttributeMaxDynamicSharedMemorySize, GEMM_SMEM);
    cudaFuncSetAttribute(flash_attn_kernel,
                         cudaFuncAttributeMaxDynamicSharedMemorySize, FA_SMEM);

    // convert inputs
    split_kernel<<<(M_ * C_ + 255) / 256, 256>>>(x, xh, xl, M_ * C_, 1.0f);
    transpose_split_kernel<<<dim3(H_ * D_ / 32, C_ / 32), dim3(32, 8)>>>(Wq, wqh, wql, C_, H_ * D_);
    transpose_split_kernel<<<dim3(G_ * D_ / 32, C_ / 32), dim3(32, 8)>>>(Wk, wkh, wkl, C_, G_ * D_);
    transpose_split_kernel<<<dim3(G_ * D_ / 32, C_ / 32), dim3(32, 8)>>>(Wv, wvh, wvl, C_, G_ * D_);
    transpose_split_kernel<<<dim3(C_ / 32, (H_ * D_) / 32), dim3(32, 8)>>>(Wo, woh, wol, H_ * D_, C_);

    // projections
    gemm_mma_kernel<<<dim3((H_ * D_) / 128, M_ / 128, 1), 256, GEMM_SMEM>>>(
        xh, xl, wqh, wql, wqh, wql, nullptr, q, q, H_ * D_, C_);
    gemm_mma_kernel<<<dim3((G_ * D_) / 128, M_ / 128, 2), 256, GEMM_SMEM>>>(
        xh, xl, wkh, wkl, wvh, wvl, nullptr, k, v, G_ * D_, C_);

    // RoPE (fp32), then split q (scale folded), k, v to bf16 hi/lo
    rope_kernel<<<(M_ * H_ * 64 + 255) / 256, 256>>>(q, H_, M_ * H_ * 64);
    rope_kernel<<<(M_ * G_ * 64 + 255) / 256, 256>>>(k, G_, M_ * G_ * 64);
    const float scale = 0.08838834764831845f;   // 1/sqrt(128)
    split_kernel<<<(M_ * H_ * D_ + 255) / 256, 256>>>(q, qh, ql, M_ * H_ * D_, scale);
    split_kernel<<<(M_ * G_ * D_ + 255) / 256, 256>>>(k, kh, kl, M_ * G_ * D_, 1.0f);
    split_kernel<<<(M_ * G_ * D_ + 255) / 256, 256>>>(v, vh, vl, M_ * G_ * D_, 1.0f);

    // flash attention (writes bf16 hi/lo directly)
    flash_attn_kernel<<<dim3(T_ / 64, H_, B_), 128, FA_SMEM>>>(
        qh, ql, kh, kl, vh, vl, ath, atl);

    // output projection + bias
    gemm_mma_kernel<<<dim3(C_ / 128, M_ / 128, 1), 256, GEMM_SMEM>>>(
        ath, atl, woh, wol, woh, wol, bo, out, out, C_, H_ * D_);
}

// round 9
// speedup vs baseline: 3.9233x; 1.0433x over previous
#include <cuda_runtime.h>
#include <cuda_bf16.h>
#include <math.h>
#include <stdint.h>

#define B_  2
#define T_  1024
#define C_  4096
#define H_  32
#define G_  8
#define D_  128
#define M_  (B_*T_)          // 2048 rows

// ---------------- scratch (__device__ globals; no allocs allowed) ----------
__device__ __nv_bfloat16 g_xh [M_ * C_];
__device__ __nv_bfloat16 g_xl [M_ * C_];
__device__ __nv_bfloat16 g_ath[M_ * C_];
__device__ __nv_bfloat16 g_atl[M_ * C_];
__device__ __nv_bfloat16 g_qh [M_ * H_ * D_];
__device__ __nv_bfloat16 g_ql [M_ * H_ * D_];
__device__ __nv_bfloat16 g_kh [M_ * G_ * D_];
__device__ __nv_bfloat16 g_kl [M_ * G_ * D_];
__device__ __nv_bfloat16 g_vh [M_ * G_ * D_];
__device__ __nv_bfloat16 g_vl [M_ * G_ * D_];
// transposed weights, [N, K] K-major, bf16 hi/lo
__device__ __nv_bfloat16 g_wqh[(H_*D_) * C_];
__device__ __nv_bfloat16 g_wql[(H_*D_) * C_];
__device__ __nv_bfloat16 g_wkh[(G_*D_) * C_];
__device__ __nv_bfloat16 g_wkl[(G_*D_) * C_];
__device__ __nv_bfloat16 g_wvh[(G_*D_) * C_];
__device__ __nv_bfloat16 g_wvl[(G_*D_) * C_];
__device__ __nv_bfloat16 g_woh[C_ * (H_*D_)];
__device__ __nv_bfloat16 g_wol[C_ * (H_*D_)];

// ---------------- helpers ---------------------------------------------------
__device__ __forceinline__ uint32_t smem_u32(const void* p) {
    uint32_t a;
    asm("{ .reg .u64 t; cvta.to.shared.u64 t, %1; cvt.u32.u64 %0, t; }"
        : "=r"(a) : "l"(p));
    return a;
}
__device__ __forceinline__ void cp16(uint32_t dst, const void* src) {
    asm volatile("cp.async.cg.shared.global [%0], [%1], 16;"
                 :: "r"(dst), "l"(src) : "memory");
}
__device__ __forceinline__ void cp_commit() {
    asm volatile("cp.async.commit_group;" ::: "memory");
}
template <int N>
__device__ __forceinline__ void cp_wait() {
    asm volatile("cp.async.wait_group %0;" :: "n"(N) : "memory");
}
__device__ __forceinline__ void mma_bf16(float* c, const uint32_t* a, const uint32_t* b) {
    asm volatile(
        "mma.sync.aligned.m16n8k16.row.col.f32.bf16.bf16.f32 "
        "{%0,%1,%2,%3}, {%4,%5,%6,%7}, {%8,%9}, {%0,%1,%2,%3};"
        : "+f"(c[0]), "+f"(c[1]), "+f"(c[2]), "+f"(c[3])
        : "r"(a[0]), "r"(a[1]), "r"(a[2]), "r"(a[3]), "r"(b[0]), "r"(b[1]));
}
__device__ __forceinline__ void ldsm4(uint32_t* r, uint32_t a) {
    asm volatile("ldmatrix.sync.aligned.m8n8.x4.shared.b16 {%0,%1,%2,%3}, [%4];"
        : "=r"(r[0]), "=r"(r[1]), "=r"(r[2]), "=r"(r[3]) : "r"(a));
}
__device__ __forceinline__ void ldsm4t(uint32_t* r, uint32_t a) {
    asm volatile("ldmatrix.sync.aligned.m8n8.x4.trans.shared.b16 {%0,%1,%2,%3}, [%4];"
        : "=r"(r[0]), "=r"(r[1]), "=r"(r[2]), "=r"(r[3]) : "r"(a));
}
__device__ __forceinline__ uint32_t packbf(float a, float b) {
    __nv_bfloat162 t;
    t.x = __float2bfloat16(a);
    t.y = __float2bfloat16(b);
    return *(uint32_t*)&t;
}

// ---------------- common GEMM tile config ----------------------------------
#define SA 40
#define MAT_BYTES (128 * SA * 2)
#define STAGE_BYTES (4 * MAT_BYTES)
#define GEMM_SMEM (2 * STAGE_BYTES)

// Shared mainloop macro body is written inline in both kernels (identical math).

// ---------------------------------------------------------------------------
// Fused QKV projection GEMM: A = x (bf16 hi/lo), B in {Wq,Wk,Wv}.
// grid.x in [0,48): [0,32) Q-tiles, [32,40) K-tiles, [40,48) V-tiles.
// Epilogue: RoPE (Q,K) + softmax scale (Q) + bf16 hi/lo split, direct store.
// ---------------------------------------------------------------------------
__global__ __launch_bounds__(256, 2)
void qkv_gemm_kernel(const __nv_bfloat16* __restrict__ xh_, const __nv_bfloat16* __restrict__ xl_,
                     const __nv_bfloat16* __restrict__ wqh_, const __nv_bfloat16* __restrict__ wql_,
                     const __nv_bfloat16* __restrict__ wkh_, const __nv_bfloat16* __restrict__ wkl_,
                     const __nv_bfloat16* __restrict__ wvh_, const __nv_bfloat16* __restrict__ wvl_,
                     __nv_bfloat16* __restrict__ qh_, __nv_bfloat16* __restrict__ ql_,
                     __nv_bfloat16* __restrict__ kh_, __nv_bfloat16* __restrict__ kl_,
                     __nv_bfloat16* __restrict__ vh_, __nv_bfloat16* __restrict__ vl_)
{
    extern __shared__ char sm[];
    const uint32_t smb = smem_u32(sm);
    const int tid  = threadIdx.x;
    const int lane = tid & 31;
    const int w    = tid >> 5;
    const int wm   = w & 3;
    const int wn   = w >> 2;
    const int gg   = lane >> 2;
    const int tt   = lane & 3;
    const int m0   = blockIdx.y * 128;
    const int bx   = blockIdx.x;

    const __nv_bfloat16 *Bh, *Bl;
    __nv_bfloat16 *OH, *OL;
    int n0, Nmat, rope;
    float scale;
    if (bx < 32)      { Bh = wqh_; Bl = wql_; OH = qh_; OL = ql_; n0 = bx * 128;        Nmat = H_ * D_; rope = 1; scale = 0.08838834764831845f; }
    else if (bx < 40) { Bh = wkh_; Bl = wkl_; OH = kh_; OL = kl_; n0 = (bx - 32) * 128; Nmat = G_ * D_; rope = 1; scale = 1.f; }
    else              { Bh = wvh_; Bl = wvl_; OH = vh_; OL = vl_; n0 = (bx - 40) * 128; Nmat = G_ * D_; rope = 0; scale = 1.f; }

    const int Kdim = C_;
    const int nchunks = Kdim >> 5;
    const __nv_bfloat16* gsrc[4] = { xh_, xl_, Bh, Bl };

    auto issue_stage = [&](int c, int st) {
        const int k0 = c << 5;
#pragma unroll
        for (int j = 0; j < 8; j++) {
            const int mat = j >> 1;
            const int idx = tid + ((j & 1) << 8);
            const int r   = idx >> 2;
            const int s   = idx & 3;
            const int grow = (mat < 2) ? (m0 + r) : (n0 + r);
            const __nv_bfloat16* src = gsrc[mat] + (size_t)grow * Kdim + k0 + s * 8;
            const uint32_t dst = smb + st * STAGE_BYTES + mat * MAT_BYTES + r * (SA * 2) + s * 16;
            cp16(dst, src);
        }
        cp_commit();
    };

    float acc[2][8][4];
#pragma unroll
    for (int i = 0; i < 2; i++)
#pragma unroll
        for (int j = 0; j < 8; j++)
#pragma unroll
            for (int l = 0; l < 4; l++) acc[i][j][l] = 0.f;

    const uint32_t aoff0 = (uint32_t)((wm * 32 + (lane & 7) + ((lane >> 3) & 1) * 8) * (SA * 2)
                                      + ((lane >> 4) & 1) * 16);
    const uint32_t boff0 = (uint32_t)((wn * 64 + (lane & 7) + ((lane >> 3) & 1) * 8) * (SA * 2)
                                      + ((lane >> 4) & 1) * 16);

    issue_stage(0, 0);

    for (int c = 0; c < nchunks; ++c) {
        const int st = c & 1;
        if (c + 1 < nchunks) { issue_stage(c + 1, st ^ 1); cp_wait<1>(); }
        else                 { cp_wait<0>(); }
        __syncthreads();

        const uint32_t sAh = smb + st * STAGE_BYTES;
        const uint32_t sAl = sAh + MAT_BYTES;
        const uint32_t sBh = sAh + 2 * MAT_BYTES;
        const uint32_t sBl = sAh + 3 * MAT_BYTES;

#pragma unroll
        for (int k16 = 0; k16 < 32; k16 += 16) {
            uint32_t ah[2][4], al[2][4];
#pragma unroll
            for (int mt = 0; mt < 2; mt++) {
                const uint32_t ao = aoff0 + mt * 16 * (SA * 2) + k16 * 2;
                ldsm4(ah[mt], sAh + ao);
                ldsm4(al[mt], sAl + ao);
            }
#pragma unroll
            for (int nt2 = 0; nt2 < 4; nt2++) {
                const uint32_t bo = boff0 + nt2 * 16 * (SA * 2) + k16 * 2;
                uint32_t bh4[4], bl4[4];
                ldsm4(bh4, sBh + bo);
                ldsm4(bl4, sBl + bo);
                uint32_t bhe[2] = { bh4[0], bh4[2] }, bho[2] = { bh4[1], bh4[3] };
                uint32_t ble[2] = { bl4[0], bl4[2] }, blo[2] = { bl4[1], bl4[3] };
#pragma unroll
                for (int mt = 0; mt < 2; mt++) {
                    mma_bf16(acc[mt][2 * nt2],     ah[mt], bhe);
                    mma_bf16(acc[mt][2 * nt2],     ah[mt], ble);
                    mma_bf16(acc[mt][2 * nt2],     al[mt], bhe);
                    mma_bf16(acc[mt][2 * nt2 + 1], ah[mt], bho);
                    mma_bf16(acc[mt][2 * nt2 + 1], ah[mt], blo);
                    mma_bf16(acc[mt][2 * nt2 + 1], al[mt], bho);
                }
            }
        }
        __syncthreads();
    }

    // ---- fused epilogue: RoPE + scale + bf16 hi/lo split ----
#pragma unroll
    for (int mt = 0; mt < 2; mt++) {
#pragma unroll
        for (int nt = 0; nt < 8; nt++) {
            const int row = m0 + wm * 32 + mt * 16 + gg;       // row, row+8
            const int col = n0 + wn * 64 + nt * 8 + 2 * tt;    // even -> RoPE pair
            float a0 = acc[mt][nt][0], a1 = acc[mt][nt][1];    // (row,   col/col+1)
            float a2 = acc[mt][nt][2], a3 = acc[mt][nt][3];    // (row+8, col/col+1)
            if (rope) {
                const int d2 = (col & 127) >> 1;
                const float invf = powf(10000.0f, -(float)d2 / 64.0f);
                float s0, c0, s1, c1;
                sincosf((float)(row & (T_ - 1)) * invf, &s0, &c0);
                sincosf((float)((row + 8) & (T_ - 1)) * invf, &s1, &c1);
                const float r0 = (a0 * c0 - a1 * s0) * scale;
                const float i0 = (a0 * s0 + a1 * c0) * scale;
                const float r1 = (a2 * c1 - a3 * s1) * scale;
                const float i1 = (a2 * s1 + a3 * c1) * scale;
                a0 = r0; a1 = i0; a2 = r1; a3 = i1;
            }
            const float h0 = __bfloat162float(__float2bfloat16(a0));
            const float h1 = __bfloat162float(__float2bfloat16(a1));
            const float h2 = __bfloat162float(__float2bfloat16(a2));
            const float h3 = __bfloat162float(__float2bfloat16(a3));
            const size_t o0 = (size_t)row * Nmat + col;
            const size_t o1 = (size_t)(row + 8) * Nmat + col;
            *(uint32_t*)(OH + o0) = packbf(h0, h1);
            *(uint32_t*)(OH + o1) = packbf(h2, h3);
            *(uint32_t*)(OL + o0) = packbf(a0 - h0, a1 - h1);
            *(uint32_t*)(OL + o1) = packbf(a2 - h2, a3 - h3);
        }
    }
}

// ---------------------------------------------------------------------------
// O-projection GEMM (fp32 out + bias) — R5 kernel, single B/C.
// ---------------------------------------------------------------------------
__global__ __launch_bounds__(256, 2)
void gemm_mma_kernel(const __nv_bfloat16* __restrict__ Ah, const __nv_bfloat16* __restrict__ Al,
                     const __nv_bfloat16* __restrict__ Bh, const __nv_bfloat16* __restrict__ Bl,
                     const float* __restrict__ bias, float* __restrict__ Cm,
                     int Ndim, int Kdim)
{
    extern __shared__ char sm[];
    const uint32_t smb = smem_u32(sm);
    const int tid  = threadIdx.x;
    const int lane = tid & 31;
    const int w    = tid >> 5;
    const int wm   = w & 3;
    const int wn   = w >> 2;
    const int gg   = lane >> 2;
    const int tt   = lane & 3;
    const int m0   = blockIdx.y * 128;
    const int n0   = blockIdx.x * 128;

    const int nchunks = Kdim >> 5;
    const __nv_bfloat16* gsrc[4] = { Ah, Al, Bh, Bl };

    auto issue_stage = [&](int c, int st) {
        const int k0 = c << 5;
#pragma unroll
        for (int j = 0; j < 8; j++) {
            const int mat = j >> 1;
            const int idx = tid + ((j & 1) << 8);
            const int r   = idx >> 2;
            const int s   = idx & 3;
            const int grow = (mat < 2) ? (m0 + r) : (n0 + r);
            const __nv_bfloat16* src = gsrc[mat] + (size_t)grow * Kdim + k0 + s * 8;
            const uint32_t dst = smb + st * STAGE_BYTES + mat * MAT_BYTES + r * (SA * 2) + s * 16;
            cp16(dst, src);
        }
        cp_commit();
    };

    float acc[2][8][4];
#pragma unroll
    for (int i = 0; i < 2; i++)
#pragma unroll
        for (int j = 0; j < 8; j++)
#pragma unroll
            for (int l = 0; l < 4; l++) acc[i][j][l] = 0.f;

    const uint32_t aoff0 = (uint32_t)((wm * 32 + (lane & 7) + ((lane >> 3) & 1) * 8) * (SA * 2)
                                      + ((lane >> 4) & 1) * 16);
    const uint32_t boff0 = (uint32_t)((wn * 64 + (lane & 7) + ((lane >> 3) & 1) * 8) * (SA * 2)
                                      + ((lane >> 4) & 1) * 16);

    issue_stage(0, 0);

    for (int c = 0; c < nchunks; ++c) {
        const int st = c & 1;
        if (c + 1 < nchunks) { issue_stage(c + 1, st ^ 1); cp_wait<1>(); }
        else                 { cp_wait<0>(); }
        __syncthreads();

        const uint32_t sAh = smb + st * STAGE_BYTES;
        const uint32_t sAl = sAh + MAT_BYTES;
        const uint32_t sBh = sAh + 2 * MAT_BYTES;
        const uint32_t sBl = sAh + 3 * MAT_BYTES;

#pragma unroll
        for (int k16 = 0; k16 < 32; k16 += 16) {
            uint32_t ah[2][4], al[2][4];
#pragma unroll
            for (int mt = 0; mt < 2; mt++) {
                const uint32_t ao = aoff0 + mt * 16 * (SA * 2) + k16 * 2;
                ldsm4(ah[mt], sAh + ao);
                ldsm4(al[mt], sAl + ao);
            }
#pragma unroll
            for (int nt2 = 0; nt2 < 4; nt2++) {
                const uint32_t bo = boff0 + nt2 * 16 * (SA * 2) + k16 * 2;
                uint32_t bh4[4], bl4[4];
                ldsm4(bh4, sBh + bo);
                ldsm4(bl4, sBl + bo);
                uint32_t bhe[2] = { bh4[0], bh4[2] }, bho[2] = { bh4[1], bh4[3] };
                uint32_t ble[2] = { bl4[0], bl4[2] }, blo[2] = { bl4[1], bl4[3] };
#pragma unroll
                for (int mt = 0; mt < 2; mt++) {
                    mma_bf16(acc[mt][2 * nt2],     ah[mt], bhe);
                    mma_bf16(acc[mt][2 * nt2],     ah[mt], ble);
                    mma_bf16(acc[mt][2 * nt2],     al[mt], bhe);
                    mma_bf16(acc[mt][2 * nt2 + 1], ah[mt], bho);
                    mma_bf16(acc[mt][2 * nt2 + 1], ah[mt], blo);
                    mma_bf16(acc[mt][2 * nt2 + 1], al[mt], bho);
                }
            }
        }
        __syncthreads();
    }

#pragma unroll
    for (int mt = 0; mt < 2; mt++) {
#pragma unroll
        for (int nt = 0; nt < 8; nt++) {
            const int row = m0 + wm * 32 + mt * 16 + gg;
            const int col = n0 + wn * 64 + nt * 8 + 2 * tt;
            float2 v0 = make_float2(acc[mt][nt][0] + bias[col], acc[mt][nt][1] + bias[col + 1]);
            float2 v1 = make_float2(acc[mt][nt][2] + bias[col], acc[mt][nt][3] + bias[col + 1]);
            *(float2*)(Cm + (size_t)row * Ndim + col)       = v0;
            *(float2*)(Cm + (size_t)(row + 8) * Ndim + col) = v1;
        }
    }
}

// ---------------- fp32 -> bf16 hi/lo split ---------------------------------
__global__ void split_kernel(const float* __restrict__ src,
                             __nv_bfloat16* __restrict__ hi,
                             __nv_bfloat16* __restrict__ lo, int n)
{
    int i = blockIdx.x * blockDim.x + threadIdx.x;
    if (i >= n) return;
    float a = src[i];
    __nv_bfloat16 h = __float2bfloat16(a);
    hi[i] = h;
    lo[i] = __float2bfloat16(a - __bfloat162float(h));
}

// ---------------------------------------------------------------------------
// Merged transpose+split of all 4 weight matrices. Flat 1D grid of 32x32 tiles:
// Wq 16384 | Wk 4096 | Wv 4096 | Wo 16384  (total 40960 tiles)
// ---------------------------------------------------------------------------
__global__ void transpose_split_all_kernel(
    const float* __restrict__ Wq, const float* __restrict__ Wk,
    const float* __restrict__ Wv, const float* __restrict__ Wo,
    __nv_bfloat16* __restrict__ wqh, __nv_bfloat16* __restrict__ wql,
    __nv_bfloat16* __restrict__ wkh, __nv_bfloat16* __restrict__ wkl,
    __nv_bfloat16* __restrict__ wvh, __nv_bfloat16* __restrict__ wvl,
    __nv_bfloat16* __restrict__ woh, __nv_bfloat16* __restrict__ wol)
{
    __shared__ float t[32][33];
    const int tile = blockIdx.x;
    const float* W;
    __nv_bfloat16 *Th, *Tl;
    int Kd, Nd, l;
    if (tile < 16384)      { W = Wq; Th = wqh; Tl = wql; Kd = C_;      Nd = H_ * D_; l = tile; }
    else if (tile < 20480) { W = Wk; Th = wkh; Tl = wkl; Kd = C_;      Nd = G_ * D_; l = tile - 16384; }
    else if (tile < 24576) { W = Wv; Th = wvh; Tl = wvl; Kd = C_;      Nd = G_ * D_; l = tile - 20480; }
    else                   { W = Wo; Th = woh; Tl = wol; Kd = H_ * D_; Nd = C_;      l = tile - 24576; }
    const int nx = Nd >> 5;
    const int n0 = (l % nx) * 32, k0 = (l / nx) * 32;
    const int tx = threadIdx.x, ty = threadIdx.y;
#pragma unroll
    for (int j = 0; j < 32; j += 8)
        t[ty + j][tx] = W[(size_t)(k0 + ty + j) * Nd + n0 + tx];
    __syncthreads();
#pragma unroll
    for (int j = 0; j < 32; j += 8) {
        float a = t[tx][ty + j];
        __nv_bfloat16 h = __float2bfloat16(a);
        size_t o = (size_t)(n0 + ty + j) * Kd + k0 + tx;
        Th[o] = h;
        Tl[o] = __float2bfloat16(a - __bfloat162float(h));
    }
}

// ---------------------------------------------------------------------------
// Flash attention, bf16x3 HMMA (unchanged from R6).
// ---------------------------------------------------------------------------
#define FA_ROW 272
#define FA_MAT (64 * FA_ROW)
#define FA_SMEM (6 * FA_MAT)

__global__ __launch_bounds__(128, 2)
void flash_attn_kernel(const __nv_bfloat16* __restrict__ qh, const __nv_bfloat16* __restrict__ ql,
                       const __nv_bfloat16* __restrict__ kh, const __nv_bfloat16* __restrict__ kl,
                       const __nv_bfloat16* __restrict__ vh, const __nv_bfloat16* __restrict__ vl,
                       __nv_bfloat16* __restrict__ oh, __nv_bfloat16* __restrict__ ol)
{
    extern __shared__ char sm[];
    const uint32_t smb = smem_u32(sm);
    const uint32_t sQh = smb,            sQl = smb + FA_MAT;
    const uint32_t sKh = smb + 2*FA_MAT, sKl = smb + 3*FA_MAT;
    const uint32_t sVh = smb + 4*FA_MAT, sVl = smb + 5*FA_MAT;
    const int tid = threadIdx.x, lane = tid & 31, w = tid >> 5;
    const int gg = lane >> 2, tt = lane & 3;
    const int tq = blockIdx.x, h = blockIdx.y, b = blockIdx.z, g = h >> 2;
    const int qbase = tq * 64;

    const uint32_t lrow = (lane & 7) + ((lane >> 3) & 1) * 8;
    const uint32_t lcol16 = ((lane >> 4) & 1) * 16;

#pragma unroll
    for (int j = 0; j < 16; j++) {
        const int i = tid + j * 128;
        const int matlo = i >> 10, idx = i & 1023, r = idx >> 4, s = idx & 15;
        const __nv_bfloat16* src = (matlo ? ql : qh)
            + (((size_t)b * T_ + qbase + r) * H_ + h) * D_ + s * 8;
        cp16((matlo ? sQl : sQh) + r * FA_ROW + s * 16, src);
    }
    cp_commit();

    auto loadK = [&](int s0) {
#pragma unroll
        for (int j = 0; j < 16; j++) {
            const int i = tid + j * 128;
            const int matlo = i >> 10, idx = i & 1023, r = idx >> 4, s = idx & 15;
            const __nv_bfloat16* src = (matlo ? kl : kh)
                + (((size_t)b * T_ + s0 + r) * G_ + g) * D_ + s * 8;
            cp16((matlo ? sKl : sKh) + r * FA_ROW + s * 16, src);
        }
        cp_commit();
    };
    auto loadV = [&](int s0) {
#pragma unroll
        for (int j = 0; j < 16; j++) {
            const int i = tid + j * 128;
            const int matlo = i >> 10, idx = i & 1023, r = idx >> 4, s = idx & 15;
            const __nv_bfloat16* src = (matlo ? vl : vh)
                + (((size_t)b * T_ + s0 + r) * G_ + g) * D_ + s * 8;
            cp16((matlo ? sVl : sVh) + r * FA_ROW + s * 16, src);
        }
        cp_commit();
    };

    loadK(0);
    loadV(0);
    cp_wait<1>();
    __syncthreads();

    uint32_t qfh[8][4], qfl[8][4];
    const uint32_t qoff = (w * 16 + lrow) * FA_ROW + lcol16;
#pragma unroll
    for (int k16 = 0; k16 < 8; k16++) {
        ldsm4(qfh[k16], sQh + qoff + k16 * 32);
        ldsm4(qfl[k16], sQl + qoff + k16 * 32);
    }

    float O[16][4];
#pragma unroll
    for (int i = 0; i < 16; i++)
#pragma unroll
        for (int j = 0; j < 4; j++) O[i][j] = 0.f;
    float mrow[2] = { -1e30f, -1e30f }, lrow_s[2] = { 0.f, 0.f };

    const int nch = tq + 1;
    for (int c = 0; c < nch; c++) {
        const int s0 = c * 64;

        float S[8][4];
#pragma unroll
        for (int i = 0; i < 8; i++)
#pragma unroll
            for (int j = 0; j < 4; j++) S[i][j] = 0.f;

#pragma unroll
        for (int k16 = 0; k16 < 8; k16++) {
#pragma unroll
            for (int nt2 = 0; nt2 < 4; nt2++) {
                const uint32_t bo = (nt2 * 16 + lrow) * FA_ROW + k16 * 32 + lcol16;
                uint32_t bh4[4], bl4[4];
                ldsm4(bh4, sKh + bo);
                ldsm4(bl4, sKl + bo);
                uint32_t bhe[2] = { bh4[0], bh4[2] }, bho[2] = { bh4[1], bh4[3] };
                uint32_t ble[2] = { bl4[0], bl4[2] }, blo[2] = { bl4[1], bl4[3] };
                mma_bf16(S[2 * nt2],     qfh[k16], bhe);
                mma_bf16(S[2 * nt2],     qfh[k16], ble);
                mma_bf16(S[2 * nt2],     qfl[k16], bhe);
                mma_bf16(S[2 * nt2 + 1], qfh[k16], bho);
                mma_bf16(S[2 * nt2 + 1], qfh[k16], blo);
                mma_bf16(S[2 * nt2 + 1], qfl[k16], bho);
            }
        }

        if (c == tq) {
#pragma unroll
            for (int nt = 0; nt < 8; nt++)
#pragma unroll
                for (int ci = 0; ci < 4; ci++) {
                    const int s = s0 + nt * 8 + 2 * tt + (ci & 1);
                    const int qr = qbase + w * 16 + gg + 8 * (ci >> 1);
                    if (s > qr) S[nt][ci] = -1e30f;
                }
        }

        float mnew[2];
#pragma unroll
        for (int r = 0; r < 2; r++) {
            float mx = mrow[r];
#pragma unroll
            for (int nt = 0; nt < 8; nt++)
                mx = fmaxf(mx, fmaxf(S[nt][2 * r], S[nt][2 * r + 1]));
            mx = fmaxf(mx, __shfl_xor_sync(0xffffffffu, mx, 1));
            mx = fmaxf(mx, __shfl_xor_sync(0xffffffffu, mx, 2));
            mnew[r] = mx;
            const float alpha = __expf(mrow[r] - mx);
            lrow_s[r] *= alpha;
            mrow[r] = mx;
#pragma unroll
            for (int dt = 0; dt < 16; dt++) {
                O[dt][2 * r]     *= alpha;
                O[dt][2 * r + 1] *= alpha;
            }
        }

        uint32_t Ph[4][4], Pl[4][4];
        float sum0 = 0.f, sum1 = 0.f;
#pragma unroll
        for (int ci16 = 0; ci16 < 4; ci16++) {
#pragma unroll
            for (int half = 0; half < 2; half++) {
                const int nt = 2 * ci16 + half;
                float p0 = __expf(S[nt][0] - mnew[0]);
                float p1 = __expf(S[nt][1] - mnew[0]);
                float p2 = __expf(S[nt][2] - mnew[1]);
                float p3 = __expf(S[nt][3] - mnew[1]);
                sum0 += p0 + p1;
                sum1 += p2 + p3;
                float h0 = __bfloat162float(__float2bfloat16(p0));
                float h1 = __bfloat162float(__float2bfloat16(p1));
                float h2 = __bfloat162float(__float2bfloat16(p2));
                float h3 = __bfloat162float(__float2bfloat16(p3));
                Ph[ci16][0 + 2 * half] = packbf(h0, h1);
                Ph[ci16][1 + 2 * half] = packbf(h2, h3);
                Pl[ci16][0 + 2 * half] = packbf(p0 - h0, p1 - h1);
                Pl[ci16][1 + 2 * half] = packbf(p2 - h2, p3 - h3);
            }
        }
        sum0 += __shfl_xor_sync(0xffffffffu, sum0, 1);
        sum0 += __shfl_xor_sync(0xffffffffu, sum0, 2);
        sum1 += __shfl_xor_sync(0xffffffffu, sum1, 1);
        sum1 += __shfl_xor_sync(0xffffffffu, sum1, 2);
        lrow_s[0] += sum0;
        lrow_s[1] += sum1;

        __syncthreads();
        if (c + 1 < nch) { loadK(s0 + 64); cp_wait<1>(); }
        else             { cp_wait<0>(); }
        __syncthreads();

#pragma unroll
        for (int dt2 = 0; dt2 < 8; dt2++) {
#pragma unroll
            for (int ci16 = 0; ci16 < 4; ci16++) {
                const uint32_t vo = (ci16 * 16 + lrow) * FA_ROW + dt2 * 32 + lcol16;
                uint32_t vfh[4], vfl[4];
                ldsm4t(vfh, sVh + vo);
                ldsm4t(vfl, sVl + vo);
                uint32_t vhe[2] = { vfh[0], vfh[1] }, vho[2] = { vfh[2], vfh[3] };
                uint32_t vle[2] = { vfl[0], vfl[1] }, vlo[2] = { vfl[2], vfl[3] };
                mma_bf16(O[2 * dt2],     Ph[ci16], vhe);
                mma_bf16(O[2 * dt2],     Pl[ci16], vhe);
                mma_bf16(O[2 * dt2],     Ph[ci16], vle);
                mma_bf16(O[2 * dt2 + 1], Ph[ci16], vho);
                mma_bf16(O[2 * dt2 + 1], Pl[ci16], vho);
                mma_bf16(O[2 * dt2 + 1], Ph[ci16], vlo);
            }
        }

        __syncthreads();
        if (c + 1 < nch) {
            loadV(s0 + 64);
            cp_wait<1>();
            __syncthreads();
        }
    }

    const float inv0 = 1.f / lrow_s[0], inv1 = 1.f / lrow_s[1];
    const int q0 = qbase + w * 16 + gg;
#pragma unroll
    for (int dt = 0; dt < 16; dt++) {
        const int col = dt * 8 + 2 * tt;
        const size_t o0 = (((size_t)b * T_ + q0) * H_ + h) * D_ + col;
        const size_t o1 = (((size_t)b * T_ + q0 + 8) * H_ + h) * D_ + col;
        float a0 = O[dt][0] * inv0, a1 = O[dt][1] * inv0;
        float a2 = O[dt][2] * inv1, a3 = O[dt][3] * inv1;
        float h0 = __bfloat162float(__float2bfloat16(a0));
        float h1 = __bfloat162float(__float2bfloat16(a1));
        float h2 = __bfloat162float(__float2bfloat16(a2));
        float h3 = __bfloat162float(__float2bfloat16(a3));
        *(uint32_t*)(oh + o0) = packbf(h0, h1);
        *(uint32_t*)(oh + o1) = packbf(h2, h3);
        *(uint32_t*)(ol + o0) = packbf(a0 - h0, a1 - h1);
        *(uint32_t*)(ol + o1) = packbf(a2 - h2, a3 - h3);
    }
}

// ---------------------------------------------------------------------------
extern "C" void kernel_launch(void* const* d_in, const int* in_sizes, int n_in,
                              void* d_out, int out_size)
{
    const float* x  = (const float*)d_in[0];
    const float* Wq = (const float*)d_in[1];
    const float* Wk = (const float*)d_in[2];
    const float* Wv = (const float*)d_in[3];
    const float* Wo = (const float*)d_in[4];
    const float* bo = (const float*)d_in[5];
    float* out = (float*)d_out;

    __nv_bfloat16 *xh, *xl, *ath, *atl, *qh, *ql, *kh, *kl, *vh, *vl;
    __nv_bfloat16 *wqh, *wql, *wkh, *wkl, *wvh, *wvl, *woh, *wol;
    cudaGetSymbolAddress((void**)&xh,  g_xh);
    cudaGetSymbolAddress((void**)&xl,  g_xl);
    cudaGetSymbolAddress((void**)&ath, g_ath);
    cudaGetSymbolAddress((void**)&atl, g_atl);
    cudaGetSymbolAddress((void**)&qh,  g_qh);
    cudaGetSymbolAddress((void**)&ql,  g_ql);
    cudaGetSymbolAddress((void**)&kh,  g_kh);
    cudaGetSymbolAddress((void**)&kl,  g_kl);
    cudaGetSymbolAddress((void**)&vh,  g_vh);
    cudaGetSymbolAddress((void**)&vl,  g_vl);
    cudaGetSymbolAddress((void**)&wqh, g_wqh);
    cudaGetSymbolAddress((void**)&wql, g_wql);
    cudaGetSymbolAddress((void**)&wkh, g_wkh);
    cudaGetSymbolAddress((void**)&wkl, g_wkl);
    cudaGetSymbolAddress((void**)&wvh, g_wvh);
    cudaGetSymbolAddress((void**)&wvl, g_wvl);
    cudaGetSymbolAddress((void**)&woh, g_woh);
    cudaGetSymbolAddress((void**)&wol, g_wol);

    cudaFuncSetAttribute(qkv_gemm_kernel,
                         cudaFuncAttributeMaxDynamicSharedMemorySize, GEMM_SMEM);
    cudaFuncSetAttribute(gemm_mma_kernel,
                         cudaFuncAttributeMaxDynamicSharedMemorySize, GEMM_SMEM);
    cudaFuncSetAttribute(flash_attn_kernel,
                         cudaFuncAttributeMaxDynamicSharedMemorySize, FA_SMEM);

    // preprocessing: split x; transpose+split all weights (one launch each)
    split_kernel<<<(M_ * C_ + 255) / 256, 256>>>(x, xh, xl, M_ * C_);
    transpose_split_all_kernel<<<40960, dim3(32, 8)>>>(
        Wq, Wk, Wv, Wo, wqh, wql, wkh, wkl, wvh, wvl, woh, wol);

    // fused QKV projection + RoPE + scale + bf16 split (one launch)
    qkv_gemm_kernel<<<dim3(48, M_ / 128), 256, GEMM_SMEM>>>(
        xh, xl, wqh, wql, wkh, wkl, wvh, wvl, qh, ql, kh, kl, vh, vl);

    // flash attention (bf16 hi/lo in and out)
    flash_attn_kernel<<<dim3(T_ / 64, H_, B_), 128, FA_SMEM>>>(
        qh, ql, kh, kl, vh, vl, ath, atl);

    // output projection + bias
    gemm_mma_kernel<<<dim3(C_ / 128, M_ / 128), 256, GEMM_SMEM>>>(
        ath, atl, woh, wol, bo, out, C_, H_ * D_);
}